// round 3
// baseline (speedup 1.0000x reference)
#include <cuda_runtime.h>
#include <math.h>

#define CB 4
#define CN 4096
#define CD 256
#define CH 8
#define CDH 32
#define CML 256
#define CBH (CB*CH)
#define CINNER 256

// ---------------- scratch (device globals; no allocation allowed) ----------
__device__ float g_Y   [CB*CN*CD];
__device__ float g_XN  [CB*CN*CD];
__device__ float g_QKV [CB*CN*3*CD];
__device__ float g_Q   [CB*CH*CN*CDH];
__device__ float g_K   [CB*CH*CN*CDH];
__device__ float g_V   [CB*CH*CN*CDH];
__device__ float g_QL  [CBH*CML*CDH];
__device__ float g_KL  [CBH*CML*CDH];
__device__ float g_A1  [(long long)CBH*CN*CML];
__device__ float g_A3  [(long long)CBH*CML*CN];   // reused as tmp1 = A1 @ pinv
__device__ float g_A2  [CBH*CML*CML];
__device__ float g_Zb  [CBH*CML*CML];
__device__ float g_Z2  [CBH*CML*CML];
__device__ float g_XZ  [CBH*CML*CML];
__device__ float g_T1  [CBH*CML*CML];
__device__ float g_T2  [CBH*CML*CML];
__device__ float g_A3V [CBH*CML*CDH];
__device__ float g_OH  [CB*CH*CN*CDH];
__device__ float g_ONBD[CB*CN*CD];
__device__ float g_HID [CB*CN*2*CD];
__device__ float g_gmax1, g_gmax2;

// ---------------- layernorm (D=256, one block per row) ---------------------
__global__ void layernorm_kernel(const float* __restrict__ x,
                                 const float* __restrict__ g,
                                 const float* __restrict__ b,
                                 float* __restrict__ out) {
    __shared__ float s[256];
    long long row = blockIdx.x;
    int tid = threadIdx.x;
    float v = x[row*CD + tid];
    s[tid] = v; __syncthreads();
    for (int o = 128; o > 0; o >>= 1) { if (tid < o) s[tid] += s[tid+o]; __syncthreads(); }
    float mu = s[0] * (1.0f/CD);
    __syncthreads();
    float d = v - mu;
    s[tid] = d*d; __syncthreads();
    for (int o = 128; o > 0; o >>= 1) { if (tid < o) s[tid] += s[tid+o]; __syncthreads(); }
    float inv = rsqrtf(s[0]*(1.0f/CD) + 1e-5f);
    out[row*CD + tid] = d * inv * g[tid] + b[tid];
}

// ---------------- generic batched SGEMM ------------------------------------
// epi: 0 none | 1 C=alpha*I-AB | 2 C=alpha*AB | 3 +bias | 4 +bias+res | 5 gelu(AB+bias)
#define BM 64
#define BN 64
#define BK 16

template<bool TB>
__global__ void __launch_bounds__(256) gemm_kernel(
    const float* __restrict__ A, const float* __restrict__ B, float* __restrict__ C,
    int M, int N, int K,
    long long sA, long long sB, long long sC,
    int epi, float alpha,
    const float* __restrict__ bias, const float* __restrict__ res)
{
    A += (long long)blockIdx.z * sA;
    B += (long long)blockIdx.z * sB;
    C += (long long)blockIdx.z * sC;

    __shared__ __align__(16) float As[BK][BM+4];
    __shared__ __align__(16) float Bs[BK][BN+4];

    int m0 = blockIdx.y * BM;
    int n0 = blockIdx.x * BN;
    int tid = threadIdx.x;
    int tx = tid & 15, ty = tid >> 4;

    float acc[4][4] = {};

    for (int k0 = 0; k0 < K; k0 += BK) {
        #pragma unroll
        for (int i = 0; i < 4; i++) {
            int ii = tid + i*256;
            int m = ii >> 4;
            int kk = ii & 15;
            int gm = m0 + m;
            As[kk][m] = (gm < M) ? A[(long long)gm*K + (k0+kk)] : 0.0f;
        }
        #pragma unroll
        for (int i = 0; i < 4; i++) {
            int ii = tid + i*256;
            if (!TB) {
                int kk = ii >> 6;
                int n  = ii & 63;
                int gn = n0 + n;
                Bs[kk][n] = (gn < N) ? B[(long long)(k0+kk)*N + gn] : 0.0f;
            } else {
                int n  = ii >> 4;
                int kk = ii & 15;
                int gn = n0 + n;
                Bs[kk][n] = (gn < N) ? B[(long long)gn*K + (k0+kk)] : 0.0f;
            }
        }
        __syncthreads();
        #pragma unroll
        for (int kk = 0; kk < BK; kk++) {
            float4 av = *reinterpret_cast<const float4*>(&As[kk][ty<<2]);
            float4 bv = *reinterpret_cast<const float4*>(&Bs[kk][tx<<2]);
            float a[4]  = {av.x, av.y, av.z, av.w};
            float bb[4] = {bv.x, bv.y, bv.z, bv.w};
            #pragma unroll
            for (int i = 0; i < 4; i++)
                #pragma unroll
                for (int j = 0; j < 4; j++)
                    acc[i][j] = fmaf(a[i], bb[j], acc[i][j]);
        }
        __syncthreads();
    }

    #pragma unroll
    for (int i = 0; i < 4; i++) {
        int gm = m0 + (ty<<2) + i;
        if (gm >= M) continue;
        #pragma unroll
        for (int j = 0; j < 4; j++) {
            int gn = n0 + (tx<<2) + j;
            if (gn >= N) continue;
            float v = acc[i][j];
            if      (epi == 1) v = ((gm==gn) ? alpha : 0.0f) - v;
            else if (epi == 2) v *= alpha;
            else if (epi == 3) v += bias[gn];
            else if (epi == 4) v += bias[gn] + res[(long long)gm*N + gn];
            else if (epi == 5) { v += bias[gn]; v = 0.5f*v*(1.0f + erff(v*0.70710678118654752f)); }
            C[(long long)gm*N + gn] = v;
        }
    }
}

// ---------------- misc elementwise ------------------------------------------
__global__ void split_heads_kernel(const float* __restrict__ qkv,
                                   float* __restrict__ q, float* __restrict__ k,
                                   float* __restrict__ v) {
    long long idx = (long long)blockIdx.x*256 + threadIdx.x; // over CB*CH*CN*CDH
    int d = idx & 31;
    long long t = idx >> 5;
    int n = (int)(t & (CN-1));
    t >>= 12;
    int h = (int)(t & 7);
    int b = (int)(t >> 3);
    long long src = ((long long)b*CN + n)*(3*CINNER) + h*CDH + d;
    q[idx] = qkv[src] * 0.17677669529663687f;   // dh^-0.5, dh=32
    k[idx] = qkv[src + CINNER];
    v[idx] = qkv[src + 2*CINNER];
}

__global__ void landmark_kernel(const float* __restrict__ q, const float* __restrict__ k,
                                float* __restrict__ ql, float* __restrict__ kl) {
    long long idx = (long long)blockIdx.x*256 + threadIdx.x; // over CBH*CML*CDH
    int d = idx & 31;
    long long t = idx >> 5;
    int m = (int)(t & (CML-1));
    long long bh = t >> 8;
    long long base = (bh*CN + (long long)m*16)*CDH + d;
    float sq = 0.f, sk = 0.f;
    #pragma unroll
    for (int j = 0; j < 16; j++) { sq += q[base + j*CDH]; sk += k[base + j*CDH]; }
    ql[idx] = sq * 0.0625f;
    kl[idx] = sk * 0.0625f;
}

__global__ void softmax_kernel(float* __restrict__ x, int L) {
    __shared__ float s[256];
    long long row = blockIdx.x;
    float* p = x + row*(long long)L;
    int tid = threadIdx.x;
    float mx = -3.4e38f;
    for (int j = tid; j < L; j += 256) mx = fmaxf(mx, p[j]);
    s[tid] = mx; __syncthreads();
    for (int o = 128; o > 0; o >>= 1) { if (tid < o) s[tid] = fmaxf(s[tid], s[tid+o]); __syncthreads(); }
    mx = s[0]; __syncthreads();
    float sum = 0.f;
    for (int j = tid; j < L; j += 256) { float e = __expf(p[j]-mx); p[j] = e; sum += e; }
    s[tid] = sum; __syncthreads();
    for (int o = 128; o > 0; o >>= 1) { if (tid < o) s[tid] += s[tid+o]; __syncthreads(); }
    float inv = 1.0f / s[0];
    for (int j = tid; j < L; j += 256) p[j] *= inv;
}

// ---------------- pinv scale (GLOBAL max across B,H) ------------------------
__global__ void zero_gmax_kernel() { g_gmax1 = 0.f; g_gmax2 = 0.f; }

__global__ void abs_rowsum_max_kernel(const float* __restrict__ x) {
    __shared__ float s[256];
    long long row = blockIdx.x; // CBH*CML
    int tid = threadIdx.x;
    float v = fabsf(x[row*CML + tid]);
    s[tid] = v; __syncthreads();
    for (int o = 128; o > 0; o >>= 1) { if (tid < o) s[tid] += s[tid+o]; __syncthreads(); }
    if (tid == 0) atomicMax((int*)&g_gmax1, __float_as_int(s[0]));
}

__global__ void abs_colsum_max_kernel(const float* __restrict__ x) {
    const float* p = x + (long long)blockIdx.x*CML*CML;
    int j = threadIdx.x;
    float s = 0.f;
    for (int i = 0; i < CML; i++) s += fabsf(p[i*CML + j]);
    atomicMax((int*)&g_gmax2, __float_as_int(s));
}

__global__ void zinit_kernel(const float* __restrict__ x, float* __restrict__ z) {
    long long idx = (long long)blockIdx.x*256 + threadIdx.x; // CBH*CML*CML
    int j = (int)(idx & 255);
    int i = (int)((idx >> 8) & 255);
    long long bh = idx >> 16;
    float denom = g_gmax1 * g_gmax2;
    z[idx] = x[(bh << 16) + ((long long)j << 8) + i] / denom;
}

__global__ void idsub_kernel(const float* __restrict__ a, float* __restrict__ c, float alpha) {
    long long idx = (long long)blockIdx.x*256 + threadIdx.x;
    int j = (int)(idx & 255);
    int i = (int)((idx >> 8) & 255);
    c[idx] = ((i==j) ? alpha : 0.0f) - a[idx];
}

// ---------------- depthwise conv (k=33, pad=16) + merge ---------------------
__global__ void conv_add_kernel(const float* __restrict__ v, const float* __restrict__ w,
                                float* __restrict__ oh) {
    long long idx = (long long)blockIdx.x*256 + threadIdx.x; // CB*CH*CN*CDH
    int d = (int)(idx & 31);
    long long t = idx >> 5;
    int n = (int)(t & (CN-1));
    long long bh = t >> 12;
    int h = (int)(bh & 7);
    const float* wp = w + h*33;
    const float* vp = v + bh*(long long)CN*CDH + d;
    float s = 0.f;
    #pragma unroll
    for (int tt = 0; tt < 33; tt++) {
        int nn = n + tt - 16;
        if (nn >= 0 && nn < CN) s += vp[(long long)nn*CDH] * wp[tt];
    }
    oh[idx] += s;
}

__global__ void merge_heads_kernel(const float* __restrict__ oh, float* __restrict__ out) {
    long long idx = (long long)blockIdx.x*256 + threadIdx.x; // CB*CN*CD
    int d = (int)(idx & 31);
    long long t = idx >> 5;
    int h = (int)(t & 7);
    t >>= 3;
    int n = (int)(t & (CN-1));
    int b = (int)(t >> 12);
    out[idx] = oh[((((long long)b*CH + h)*CN) + n)*CDH + d];
}

// ---------------- host orchestration ----------------------------------------
extern "C" void kernel_launch(void* const* d_in, const int* in_sizes, int n_in,
                              void* d_out, int out_size) {
    const float* x     = (const float*)d_in[0];
    const float* ln1_g = (const float*)d_in[1];
    const float* ln1_b = (const float*)d_in[2];
    const float* w_qkv = (const float*)d_in[3];
    const float* w_out = (const float*)d_in[4];
    const float* b_out = (const float*)d_in[5];
    const float* res_w = (const float*)d_in[6];
    const float* ln2_g = (const float*)d_in[7];
    const float* ln2_b = (const float*)d_in[8];
    const float* w1    = (const float*)d_in[9];
    const float* b1    = (const float*)d_in[10];
    const float* w2    = (const float*)d_in[11];
    const float* b2    = (const float*)d_in[12];

    float *Y,*XN,*QKV,*Q,*K,*V,*QL,*KL,*A1,*A3,*A2,*Zb,*Z2,*XZ,*T1,*T2,*A3V,*OH,*ONBD,*HID;
    cudaGetSymbolAddress((void**)&Y,   g_Y);
    cudaGetSymbolAddress((void**)&XN,  g_XN);
    cudaGetSymbolAddress((void**)&QKV, g_QKV);
    cudaGetSymbolAddress((void**)&Q,   g_Q);
    cudaGetSymbolAddress((void**)&K,   g_K);
    cudaGetSymbolAddress((void**)&V,   g_V);
    cudaGetSymbolAddress((void**)&QL,  g_QL);
    cudaGetSymbolAddress((void**)&KL,  g_KL);
    cudaGetSymbolAddress((void**)&A1,  g_A1);
    cudaGetSymbolAddress((void**)&A3,  g_A3);
    cudaGetSymbolAddress((void**)&A2,  g_A2);
    cudaGetSymbolAddress((void**)&Zb,  g_Zb);
    cudaGetSymbolAddress((void**)&Z2,  g_Z2);
    cudaGetSymbolAddress((void**)&XZ,  g_XZ);
    cudaGetSymbolAddress((void**)&T1,  g_T1);
    cudaGetSymbolAddress((void**)&T2,  g_T2);
    cudaGetSymbolAddress((void**)&A3V, g_A3V);
    cudaGetSymbolAddress((void**)&OH,  g_OH);
    cudaGetSymbolAddress((void**)&ONBD,g_ONBD);
    cudaGetSymbolAddress((void**)&HID, g_HID);

    cudaMemcpyAsync(Y, x, sizeof(float)*(size_t)CB*CN*CD, cudaMemcpyDeviceToDevice);

    const long long MM = (long long)CML*CML;

    for (int blk = 0; blk < 2; blk++) {
        const float* p_ln1g = ln1_g + blk*CD;
        const float* p_ln1b = ln1_b + blk*CD;
        const float* p_wqkv = w_qkv + (long long)blk*CD*3*CINNER;
        const float* p_wout = w_out + (long long)blk*CINNER*CD;
        const float* p_bout = b_out + blk*CD;
        const float* p_resw = res_w + blk*CH*33;
        const float* p_ln2g = ln2_g + blk*CD;
        const float* p_ln2b = ln2_b + blk*CD;
        const float* p_w1   = w1 + (long long)blk*CD*2*CD;
        const float* p_b1   = b1 + blk*2*CD;
        const float* p_w2   = w2 + (long long)blk*2*CD*CD;
        const float* p_b2   = b2 + blk*CD;

        // LN1 -> XN
        layernorm_kernel<<<CB*CN, 256>>>(Y, p_ln1g, p_ln1b, XN);

        // QKV = XN @ w_qkv  [16384, 768]
        gemm_kernel<false><<<dim3(12, 256, 1), 256>>>(XN, p_wqkv, QKV,
            CB*CN, 3*CINNER, CD, 0, 0, 0, 0, 0.f, nullptr, nullptr);

        split_heads_kernel<<<(CB*CH*CN*CDH)/256, 256>>>(QKV, Q, K, V);
        landmark_kernel<<<(CBH*CML*CDH)/256, 256>>>(Q, K, QL, KL);

        // attn1 = softmax(Q @ KL^T)  [bh][4096, 256]
        gemm_kernel<true><<<dim3(4, 64, CBH), 256>>>(Q, KL, A1,
            CN, CML, CDH, (long long)CN*CDH, (long long)CML*CDH, (long long)CN*CML,
            0, 0.f, nullptr, nullptr);
        softmax_kernel<<<CBH*CN, 256>>>(A1, CML);

        // attn2 = softmax(QL @ KL^T) [bh][256, 256]
        gemm_kernel<true><<<dim3(4, 4, CBH), 256>>>(QL, KL, A2,
            CML, CML, CDH, (long long)CML*CDH, (long long)CML*CDH, MM,
            0, 0.f, nullptr, nullptr);
        softmax_kernel<<<CBH*CML, 256>>>(A2, CML);

        // attn3 = softmax(QL @ K^T)  [bh][256, 4096]
        gemm_kernel<true><<<dim3(64, 4, CBH), 256>>>(QL, K, A3,
            CML, CN, CDH, (long long)CML*CDH, (long long)CN*CDH, (long long)CML*CN,
            0, 0.f, nullptr, nullptr);
        softmax_kernel<<<CBH*CML, 256>>>(A3, CN);

        // ---- Moore-Penrose pinv of attn2 (global-max scale) ----
        zero_gmax_kernel<<<1, 1>>>();
        abs_rowsum_max_kernel<<<CBH*CML, 256>>>(A2);
        abs_colsum_max_kernel<<<CBH, 256>>>(A2);
        zinit_kernel<<<(int)((CBH*MM)/256), 256>>>(A2, Zb);

        float* zc = Zb; float* zn = Z2;
        for (int it = 0; it < 6; it++) {
            gemm_kernel<false><<<dim3(4, 4, CBH), 256>>>(A2, zc, XZ,
                CML, CML, CML, MM, MM, MM, 0, 0.f, nullptr, nullptr);
            idsub_kernel<<<(int)((CBH*MM)/256), 256>>>(XZ, T1, 7.0f);
            gemm_kernel<false><<<dim3(4, 4, CBH), 256>>>(XZ, T1, T2,
                CML, CML, CML, MM, MM, MM, 1, 15.0f, nullptr, nullptr);
            gemm_kernel<false><<<dim3(4, 4, CBH), 256>>>(XZ, T2, T1,
                CML, CML, CML, MM, MM, MM, 1, 13.0f, nullptr, nullptr);
            gemm_kernel<false><<<dim3(4, 4, CBH), 256>>>(zc, T1, zn,
                CML, CML, CML, MM, MM, MM, 2, 0.25f, nullptr, nullptr);
            float* t = zc; zc = zn; zn = t;
        }

        // A3V = attn3 @ V  [bh][256, 32]
        gemm_kernel<false><<<dim3(1, 4, CBH), 256>>>(A3, V, A3V,
            CML, CDH, CN, (long long)CML*CN, (long long)CN*CDH, (long long)CML*CDH,
            0, 0.f, nullptr, nullptr);

        // tmp1 = attn1 @ pinv  [bh][4096, 256]   (A3 buffer reused as output)
        gemm_kernel<false><<<dim3(4, 64, CBH), 256>>>(A1, zc, A3,
            CN, CML, CML, (long long)CN*CML, MM, (long long)CN*CML,
            0, 0.f, nullptr, nullptr);

        // OH = tmp1 @ A3V   [bh][4096, 32]
        gemm_kernel<false><<<dim3(1, 64, CBH), 256>>>(A3, A3V, OH,
            CN, CDH, CML, (long long)CN*CML, (long long)CML*CDH, (long long)CN*CDH,
            0, 0.f, nullptr, nullptr);

        // OH += depthwise conv(V), merge heads
        conv_add_kernel<<<(CB*CH*CN*CDH)/256, 256>>>(V, p_resw, OH);
        merge_heads_kernel<<<(CB*CN*CD)/256, 256>>>(OH, ONBD);

        // Y = Y + ONBD @ w_out + b_out
        gemm_kernel<false><<<dim3(4, 256, 1), 256>>>(ONBD, p_wout, Y,
            CB*CN, CD, CINNER, 0, 0, 0, 4, 0.f, p_bout, Y);

        // MLP
        layernorm_kernel<<<CB*CN, 256>>>(Y, p_ln2g, p_ln2b, XN);
        gemm_kernel<false><<<dim3(8, 256, 1), 256>>>(XN, p_w1, HID,
            CB*CN, 2*CD, CD, 0, 0, 0, 5, 0.f, p_b1, nullptr);
        gemm_kernel<false><<<dim3(4, 256, 1), 256>>>(HID, p_w2, Y,
            CB*CN, CD, 2*CD, 0, 0, 0, 4, 0.f, p_b2, Y);
    }

    cudaMemcpyAsync(d_out, Y, sizeof(float)*(size_t)CB*CN*CD, cudaMemcpyDeviceToDevice);
}

// round 4
// speedup vs baseline: 1.8669x; 1.8669x over previous
#include <cuda_runtime.h>
#include <math.h>

#define CB 4
#define CN 4096
#define CD 256
#define CH 8
#define CDH 32
#define CML 256
#define CBH (CB*CH)
#define CINNER 256

// ---------------- scratch ----------------------------------------------------
__device__ float g_Y   [CB*CN*CD];
__device__ float g_XN  [CB*CN*CD];
__device__ float g_QKV [CB*CN*3*CD];
__device__ float g_Q   [CB*CH*CN*CDH];
__device__ float g_K   [CB*CH*CN*CDH];
__device__ float g_V   [CB*CH*CN*CDH];
__device__ float g_QL  [CBH*CML*CDH];
__device__ float g_KL  [CBH*CML*CDH];
__device__ float g_X2  [CBH*CML*CDH];
__device__ float g_A1  [(long long)CBH*CN*CML];
__device__ float g_A3  [(long long)CBH*CML*CN];
__device__ float g_A2  [CBH*CML*CML];
__device__ float g_Zb  [CBH*CML*CML];
__device__ float g_Z2  [CBH*CML*CML];
__device__ float g_XZ  [CBH*CML*CML];
__device__ float g_T1  [CBH*CML*CML];
__device__ float g_T2  [CBH*CML*CML];
__device__ float g_A3V [CBH*CML*CDH];
__device__ float g_P   [8*CBH*CML*CDH];
__device__ float g_OH  [CB*CH*CN*CDH];
__device__ float g_ONBD[CB*CN*CD];
__device__ float g_HID [CB*CN*2*CD];
__device__ float g_gmax1, g_gmax2;

// ---------------- layernorm --------------------------------------------------
__global__ void layernorm_kernel(const float* __restrict__ x,
                                 const float* __restrict__ g,
                                 const float* __restrict__ b,
                                 float* __restrict__ out) {
    __shared__ float s[256];
    long long row = blockIdx.x;
    int tid = threadIdx.x;
    float v = x[row*CD + tid];
    s[tid] = v; __syncthreads();
    for (int o = 128; o > 0; o >>= 1) { if (tid < o) s[tid] += s[tid+o]; __syncthreads(); }
    float mu = s[0] * (1.0f/CD);
    __syncthreads();
    float d = v - mu;
    s[tid] = d*d; __syncthreads();
    for (int o = 128; o > 0; o >>= 1) { if (tid < o) s[tid] += s[tid+o]; __syncthreads(); }
    float inv = rsqrtf(s[0]*(1.0f/CD) + 1e-5f);
    out[row*CD + tid] = d * inv * g[tid] + b[tid];
}

// ---------------- 128x128x8 double-buffered SGEMM ----------------------------
// EPI: 0 C=AB | 1 C=aI-AB | 2 C=a*AB | 3 C=AB,C2=aI-AB | 4 AB+bias+res | 5 gelu(AB+bias)
// Requires M%128==0, N%128==0, K%8==0.
template<int EPI>
__global__ void __launch_bounds__(256) gemm128_kernel(
    const float* __restrict__ A, const float* __restrict__ B,
    float* __restrict__ C, float* __restrict__ C2,
    int M, int N, int K,
    long long sA, long long sB, long long sC,
    float alpha, const float* __restrict__ bias, const float* __restrict__ res)
{
    A += (long long)blockIdx.z * sA;
    B += (long long)blockIdx.z * sB;
    C += (long long)blockIdx.z * sC;
    if (EPI == 3) C2 += (long long)blockIdx.z * sC;

    __shared__ float As[2][8][128];
    __shared__ float Bs[2][8][128];
    int t = threadIdx.x;
    int m0 = blockIdx.y*128, n0 = blockIdx.x*128;
    int ar = t & 127, ak = (t>>7)*4;
    int br = t >> 5,  bc = (t&31)*4;
    int tx = t & 15,  ty = t >> 4;
    const float* Ap = A + (long long)(m0+ar)*K + ak;
    const float* Bp = B + (long long)br*N + n0 + bc;
    float4 av = *(const float4*)Ap;
    float4 bv = *(const float4*)Bp;
    float acc[8][8] = {};
    int buf = 0;
    As[0][ak+0][ar]=av.x; As[0][ak+1][ar]=av.y; As[0][ak+2][ar]=av.z; As[0][ak+3][ar]=av.w;
    *(float4*)&Bs[0][br][bc] = bv;
    __syncthreads();
    for (int k0 = 8; k0 <= K; k0 += 8) {
        if (k0 < K) {
            av = *(const float4*)(Ap + k0);
            bv = *(const float4*)(Bp + (long long)k0 * N);
        }
        #pragma unroll
        for (int kk = 0; kk < 8; kk++) {
            float a[8], b[8];
            *(float4*)(a)   = *(const float4*)&As[buf][kk][ty*4];
            *(float4*)(a+4) = *(const float4*)&As[buf][kk][64+ty*4];
            *(float4*)(b)   = *(const float4*)&Bs[buf][kk][tx*4];
            *(float4*)(b+4) = *(const float4*)&Bs[buf][kk][64+tx*4];
            #pragma unroll
            for (int i = 0; i < 8; i++)
                #pragma unroll
                for (int j = 0; j < 8; j++)
                    acc[i][j] = fmaf(a[i], b[j], acc[i][j]);
        }
        if (k0 < K) {
            buf ^= 1;
            As[buf][ak+0][ar]=av.x; As[buf][ak+1][ar]=av.y;
            As[buf][ak+2][ar]=av.z; As[buf][ak+3][ar]=av.w;
            *(float4*)&Bs[buf][br][bc] = bv;
            __syncthreads();
        }
    }
    #pragma unroll
    for (int i = 0; i < 8; i++) {
        int gm = m0 + ((i < 4) ? ty*4 + i : 64 + ty*4 + (i-4));
        #pragma unroll
        for (int j = 0; j < 8; j++) {
            int gn = n0 + ((j < 4) ? tx*4 + j : 64 + tx*4 + (j-4));
            float v = acc[i][j];
            long long off = (long long)gm*N + gn;
            if (EPI == 1)      C[off] = ((gm==gn)?alpha:0.0f) - v;
            else if (EPI == 2) C[off] = alpha * v;
            else if (EPI == 4) C[off] = v + bias[gn] + res[off];
            else if (EPI == 5) { v += bias[gn]; C[off] = 0.5f*v*(1.0f + erff(v*0.70710678118654752f)); }
            else               C[off] = v;
            if (EPI == 3)      C2[off] = ((gm==gn)?alpha:0.0f) - v;
        }
    }
}

// ---------------- tf32 tensor-core batched GEMM (256x256x256 per batch) ------
// EPI: 0 C=AB | 1 C=aI-AB | 2 C=a*AB | 3 C=AB and C2=aI-AB
template<int EPI>
__global__ void __launch_bounds__(256) pinv_tc_kernel(
    const float* __restrict__ A, const float* __restrict__ B,
    float* __restrict__ C, float* __restrict__ C2, float alpha)
{
    const long long MM = (long long)CML*CML;
    A  += blockIdx.z*MM; B += blockIdx.z*MM; C += blockIdx.z*MM;
    if (EPI == 3) C2 += blockIdx.z*MM;
    int m0 = blockIdx.y*128, n0 = blockIdx.x*128;
    __shared__ unsigned As[32][132];
    __shared__ unsigned Bs[32][132];
    int t = threadIdx.x;
    int w = t >> 5, l = t & 31;
    int wm = (w >> 2)*64, wn = (w & 3)*32;
    int grp = l >> 2, qid = l & 3;
    float acc[4][4][4] = {};
    int ar  = t & 127;
    int akg = (t >> 7)*16;
    int bkr = t >> 3;
    int bn4 = (t & 7)*4;

    for (int k0 = 0; k0 < 256; k0 += 32) {
        #pragma unroll
        for (int i = 0; i < 4; i++) {
            float4 v = *(const float4*)(A + (long long)(m0+ar)*256 + k0 + akg + i*4);
            unsigned u0,u1,u2,u3;
            asm("cvt.rna.tf32.f32 %0, %1;" : "=r"(u0) : "f"(v.x));
            asm("cvt.rna.tf32.f32 %0, %1;" : "=r"(u1) : "f"(v.y));
            asm("cvt.rna.tf32.f32 %0, %1;" : "=r"(u2) : "f"(v.z));
            asm("cvt.rna.tf32.f32 %0, %1;" : "=r"(u3) : "f"(v.w));
            As[akg+i*4+0][ar]=u0; As[akg+i*4+1][ar]=u1;
            As[akg+i*4+2][ar]=u2; As[akg+i*4+3][ar]=u3;
        }
        #pragma unroll
        for (int i = 0; i < 4; i++) {
            int n = bn4 + i*32;
            float4 v = *(const float4*)(B + (long long)(k0+bkr)*256 + n0 + n);
            unsigned u0,u1,u2,u3;
            asm("cvt.rna.tf32.f32 %0, %1;" : "=r"(u0) : "f"(v.x));
            asm("cvt.rna.tf32.f32 %0, %1;" : "=r"(u1) : "f"(v.y));
            asm("cvt.rna.tf32.f32 %0, %1;" : "=r"(u2) : "f"(v.z));
            asm("cvt.rna.tf32.f32 %0, %1;" : "=r"(u3) : "f"(v.w));
            Bs[bkr][n+0]=u0; Bs[bkr][n+1]=u1; Bs[bkr][n+2]=u2; Bs[bkr][n+3]=u3;
        }
        __syncthreads();
        #pragma unroll
        for (int ks = 0; ks < 4; ks++) {
            int kb = ks*8;
            unsigned af[4][4], bf[4][2];
            #pragma unroll
            for (int mi = 0; mi < 4; mi++) {
                int mb = wm + mi*16;
                af[mi][0] = As[kb+qid  ][mb+grp  ];
                af[mi][1] = As[kb+qid  ][mb+grp+8];
                af[mi][2] = As[kb+qid+4][mb+grp  ];
                af[mi][3] = As[kb+qid+4][mb+grp+8];
            }
            #pragma unroll
            for (int ni = 0; ni < 4; ni++) {
                int nb = wn + ni*8;
                bf[ni][0] = Bs[kb+qid  ][nb+grp];
                bf[ni][1] = Bs[kb+qid+4][nb+grp];
            }
            #pragma unroll
            for (int mi = 0; mi < 4; mi++)
                #pragma unroll
                for (int ni = 0; ni < 4; ni++) {
                    asm volatile(
                        "mma.sync.aligned.m16n8k8.row.col.f32.tf32.tf32.f32 "
                        "{%0,%1,%2,%3}, {%4,%5,%6,%7}, {%8,%9}, {%0,%1,%2,%3};"
                        : "+f"(acc[mi][ni][0]), "+f"(acc[mi][ni][1]),
                          "+f"(acc[mi][ni][2]), "+f"(acc[mi][ni][3])
                        : "r"(af[mi][0]), "r"(af[mi][1]), "r"(af[mi][2]), "r"(af[mi][3]),
                          "r"(bf[ni][0]), "r"(bf[ni][1]));
                }
        }
        __syncthreads();
    }
    #pragma unroll
    for (int mi = 0; mi < 4; mi++)
        #pragma unroll
        for (int ni = 0; ni < 4; ni++)
            #pragma unroll
            for (int r = 0; r < 4; r++) {
                int gm = m0 + wm + mi*16 + grp + ((r >= 2) ? 8 : 0);
                int gn = n0 + wn + ni*8 + 2*qid + (r & 1);
                float v = acc[mi][ni][r];
                long long off = (long long)gm*256 + gn;
                if (EPI == 1)      C[off] = ((gm==gn)?alpha:0.0f) - v;
                else if (EPI == 2) C[off] = alpha * v;
                else               C[off] = v;
                if (EPI == 3)      C2[off] = ((gm==gn)?alpha:0.0f) - v;
            }
}

// ---------------- 64x64 SGEMM (B transposed) for attention logits ------------
#define BM 64
#define BN 64
#define BK 16
__global__ void __launch_bounds__(256) gemmT_kernel(
    const float* __restrict__ A, const float* __restrict__ B, float* __restrict__ C,
    int M, int N, int K,
    long long sA, long long sB, long long sC)
{
    A += (long long)blockIdx.z * sA;
    B += (long long)blockIdx.z * sB;
    C += (long long)blockIdx.z * sC;
    __shared__ __align__(16) float As[BK][BM+4];
    __shared__ __align__(16) float Bs[BK][BN+4];
    int m0 = blockIdx.y * BM;
    int n0 = blockIdx.x * BN;
    int tid = threadIdx.x;
    int tx = tid & 15, ty = tid >> 4;
    float acc[4][4] = {};
    for (int k0 = 0; k0 < K; k0 += BK) {
        #pragma unroll
        for (int i = 0; i < 4; i++) {
            int ii = tid + i*256;
            int m = ii >> 4;
            int kk = ii & 15;
            As[kk][m] = A[(long long)(m0+m)*K + (k0+kk)];
        }
        #pragma unroll
        for (int i = 0; i < 4; i++) {
            int ii = tid + i*256;
            int n  = ii >> 4;
            int kk = ii & 15;
            Bs[kk][n] = B[(long long)(n0+n)*K + (k0+kk)];
        }
        __syncthreads();
        #pragma unroll
        for (int kk = 0; kk < BK; kk++) {
            float4 av = *reinterpret_cast<const float4*>(&As[kk][ty<<2]);
            float4 bv = *reinterpret_cast<const float4*>(&Bs[kk][tx<<2]);
            float a[4]  = {av.x, av.y, av.z, av.w};
            float bb[4] = {bv.x, bv.y, bv.z, bv.w};
            #pragma unroll
            for (int i = 0; i < 4; i++)
                #pragma unroll
                for (int j = 0; j < 4; j++)
                    acc[i][j] = fmaf(a[i], bb[j], acc[i][j]);
        }
        __syncthreads();
    }
    #pragma unroll
    for (int i = 0; i < 4; i++)
        #pragma unroll
        for (int j = 0; j < 4; j++)
            C[(long long)(m0 + (ty<<2) + i)*N + n0 + (tx<<2) + j] = acc[i][j];
}

// ---------------- narrow-N (N=32) SGEMM with optional split-K ----------------
// threads = 2*BMv. Requires M%BMv==0, K%(16*KS)==0.
template<int BMv, int KS>
__global__ void gemm_n32_kernel(
    const float* __restrict__ A, const float* __restrict__ B, float* __restrict__ C,
    int M, int K, long long sA, long long sB, long long sC, long long sSlice)
{
    A += (long long)blockIdx.z * sA;
    B += (long long)blockIdx.z * sB;
    C += (long long)blockIdx.z * sC + ((KS > 1) ? (long long)blockIdx.y * sSlice : 0);
    int klen = K / KS;
    int kbeg = blockIdx.y * klen;
    __shared__ float As[16][BMv];
    __shared__ float Bs[16][32];
    int t = threadIdx.x;
    int m0 = blockIdx.x * BMv;
    int ar  = t % BMv;
    int akg = (t / BMv) * 8;
    int bkr = t >> 3, bn4 = (t & 7)*4;
    int tx = t & 7, ty = t >> 3;
    float acc[4][4] = {};
    for (int k0 = kbeg; k0 < kbeg + klen; k0 += 16) {
        #pragma unroll
        for (int i = 0; i < 2; i++) {
            float4 v = *(const float4*)(A + (long long)(m0+ar)*K + k0 + akg + i*4);
            As[akg+i*4+0][ar]=v.x; As[akg+i*4+1][ar]=v.y;
            As[akg+i*4+2][ar]=v.z; As[akg+i*4+3][ar]=v.w;
        }
        if (t < 128) {
            float4 v = *(const float4*)(B + (long long)(k0+bkr)*32 + bn4);
            *(float4*)&Bs[bkr][bn4] = v;
        }
        __syncthreads();
        #pragma unroll
        for (int kk = 0; kk < 16; kk++) {
            float4 a = *(const float4*)&As[kk][ty*4];
            float4 b = *(const float4*)&Bs[kk][tx*4];
            float aa[4] = {a.x,a.y,a.z,a.w};
            float bb[4] = {b.x,b.y,b.z,b.w};
            #pragma unroll
            for (int i = 0; i < 4; i++)
                #pragma unroll
                for (int j = 0; j < 4; j++)
                    acc[i][j] = fmaf(aa[i], bb[j], acc[i][j]);
        }
        __syncthreads();
    }
    #pragma unroll
    for (int i = 0; i < 4; i++)
        #pragma unroll
        for (int j = 0; j < 4; j++)
            C[(long long)(m0 + ty*4 + i)*32 + tx*4 + j] = acc[i][j];
}

__global__ void reduce8_kernel(const float* __restrict__ P, float* __restrict__ out) {
    long long j = (long long)blockIdx.x*256 + threadIdx.x;
    const long long S = (long long)CBH*CML*CDH;
    float s = 0.f;
    #pragma unroll
    for (int i = 0; i < 8; i++) s += P[i*S + j];
    out[j] = s;
}

// ---------------- single-pass softmaxes --------------------------------------
__global__ void softmax256_kernel(float* __restrict__ x) {
    long long row = (long long)blockIdx.x*8 + (threadIdx.x >> 5);
    int lane = threadIdx.x & 31;
    float* p = x + row*256;
    float4 a = *(float4*)(p + lane*4);
    float4 b = *(float4*)(p + 128 + lane*4);
    float m = fmaxf(fmaxf(fmaxf(a.x,a.y), fmaxf(a.z,a.w)),
                    fmaxf(fmaxf(b.x,b.y), fmaxf(b.z,b.w)));
    #pragma unroll
    for (int o = 16; o > 0; o >>= 1) m = fmaxf(m, __shfl_xor_sync(0xffffffffu, m, o));
    a.x=__expf(a.x-m); a.y=__expf(a.y-m); a.z=__expf(a.z-m); a.w=__expf(a.w-m);
    b.x=__expf(b.x-m); b.y=__expf(b.y-m); b.z=__expf(b.z-m); b.w=__expf(b.w-m);
    float s = a.x+a.y+a.z+a.w + b.x+b.y+b.z+b.w;
    #pragma unroll
    for (int o = 16; o > 0; o >>= 1) s += __shfl_xor_sync(0xffffffffu, s, o);
    float inv = 1.0f / s;
    a.x*=inv; a.y*=inv; a.z*=inv; a.w*=inv;
    b.x*=inv; b.y*=inv; b.z*=inv; b.w*=inv;
    *(float4*)(p + lane*4) = a;
    *(float4*)(p + 128 + lane*4) = b;
}

__global__ void softmax4096_kernel(float* __restrict__ x) {
    long long row = blockIdx.x;
    float* p = x + row*4096;
    int t = threadIdx.x;
    __shared__ float red[8];
    float4 v[4];
    #pragma unroll
    for (int i = 0; i < 4; i++) v[i] = *(float4*)(p + t*4 + i*1024);
    float m = -3.4e38f;
    #pragma unroll
    for (int i = 0; i < 4; i++)
        m = fmaxf(m, fmaxf(fmaxf(v[i].x, v[i].y), fmaxf(v[i].z, v[i].w)));
    #pragma unroll
    for (int o = 16; o > 0; o >>= 1) m = fmaxf(m, __shfl_xor_sync(0xffffffffu, m, o));
    if ((t & 31) == 0) red[t >> 5] = m;
    __syncthreads();
    m = red[0];
    #pragma unroll
    for (int i = 1; i < 8; i++) m = fmaxf(m, red[i]);
    float s = 0.f;
    #pragma unroll
    for (int i = 0; i < 4; i++) {
        v[i].x = __expf(v[i].x - m); v[i].y = __expf(v[i].y - m);
        v[i].z = __expf(v[i].z - m); v[i].w = __expf(v[i].w - m);
        s += v[i].x + v[i].y + v[i].z + v[i].w;
    }
    #pragma unroll
    for (int o = 16; o > 0; o >>= 1) s += __shfl_xor_sync(0xffffffffu, s, o);
    __syncthreads();
    if ((t & 31) == 0) red[t >> 5] = s;
    __syncthreads();
    s = 0.f;
    #pragma unroll
    for (int i = 0; i < 8; i++) s += red[i];
    float inv = 1.0f / s;
    #pragma unroll
    for (int i = 0; i < 4; i++) {
        v[i].x *= inv; v[i].y *= inv; v[i].z *= inv; v[i].w *= inv;
        *(float4*)(p + t*4 + i*1024) = v[i];
    }
}

// ---------------- misc elementwise -------------------------------------------
__global__ void split_heads_kernel(const float* __restrict__ qkv,
                                   float* __restrict__ q, float* __restrict__ k,
                                   float* __restrict__ v) {
    long long idx = (long long)blockIdx.x*256 + threadIdx.x;
    int d = idx & 31;
    long long t = idx >> 5;
    int n = (int)(t & (CN-1));
    t >>= 12;
    int h = (int)(t & 7);
    int b = (int)(t >> 3);
    long long src = ((long long)b*CN + n)*(3*CINNER) + h*CDH + d;
    q[idx] = qkv[src] * 0.17677669529663687f;
    k[idx] = qkv[src + CINNER];
    v[idx] = qkv[src + 2*CINNER];
}

__global__ void landmark_kernel(const float* __restrict__ q, const float* __restrict__ k,
                                float* __restrict__ ql, float* __restrict__ kl) {
    long long idx = (long long)blockIdx.x*256 + threadIdx.x;
    int d = idx & 31;
    long long t = idx >> 5;
    int m = (int)(t & (CML-1));
    long long bh = t >> 8;
    long long base = (bh*CN + (long long)m*16)*CDH + d;
    float sq = 0.f, sk = 0.f;
    #pragma unroll
    for (int j = 0; j < 16; j++) { sq += q[base + j*CDH]; sk += k[base + j*CDH]; }
    ql[idx] = sq * 0.0625f;
    kl[idx] = sk * 0.0625f;
}

// ---------------- pinv scale (GLOBAL max across B,H) -------------------------
__global__ void zero_gmax_kernel() { g_gmax1 = 0.f; g_gmax2 = 0.f; }

__global__ void abs_rowsum_max_kernel(const float* __restrict__ x) {
    __shared__ float s[256];
    long long row = blockIdx.x;
    int tid = threadIdx.x;
    float v = fabsf(x[row*CML + tid]);
    s[tid] = v; __syncthreads();
    for (int o = 128; o > 0; o >>= 1) { if (tid < o) s[tid] += s[tid+o]; __syncthreads(); }
    if (tid == 0) atomicMax((int*)&g_gmax1, __float_as_int(s[0]));
}

__global__ void abs_colsum_max_kernel(const float* __restrict__ x) {
    const float* p = x + (long long)blockIdx.x*CML*CML;
    int j = threadIdx.x;
    float s = 0.f;
    for (int i = 0; i < CML; i++) s += fabsf(p[i*CML + j]);
    atomicMax((int*)&g_gmax2, __float_as_int(s));
}

__global__ void zinit_kernel(const float* __restrict__ x, float* __restrict__ z) {
    long long idx = (long long)blockIdx.x*256 + threadIdx.x;
    int j = (int)(idx & 255);
    int i = (int)((idx >> 8) & 255);
    long long bh = idx >> 16;
    float denom = g_gmax1 * g_gmax2;
    z[idx] = x[(bh << 16) + ((long long)j << 8) + i] / denom;
}

// ---------------- depthwise conv (k=33, pad=16) + merge ----------------------
__global__ void conv_add_kernel(const float* __restrict__ v, const float* __restrict__ w,
                                float* __restrict__ oh) {
    long long idx = (long long)blockIdx.x*256 + threadIdx.x;
    int d = (int)(idx & 31);
    long long t = idx >> 5;
    int n = (int)(t & (CN-1));
    long long bh = t >> 12;
    int h = (int)(bh & 7);
    const float* wp = w + h*33;
    const float* vp = v + bh*(long long)CN*CDH + d;
    float s = 0.f;
    #pragma unroll
    for (int tt = 0; tt < 33; tt++) {
        int nn = n + tt - 16;
        if (nn >= 0 && nn < CN) s += vp[(long long)nn*CDH] * wp[tt];
    }
    oh[idx] += s;
}

__global__ void merge_heads_kernel(const float* __restrict__ oh, float* __restrict__ out) {
    long long idx = (long long)blockIdx.x*256 + threadIdx.x;
    int d = (int)(idx & 31);
    long long t = idx >> 5;
    int h = (int)(t & 7);
    t >>= 3;
    int n = (int)(t & (CN-1));
    int b = (int)(t >> 12);
    out[idx] = oh[((((long long)b*CH + h)*CN) + n)*CDH + d];
}

// ---------------- host orchestration -----------------------------------------
extern "C" void kernel_launch(void* const* d_in, const int* in_sizes, int n_in,
                              void* d_out, int out_size) {
    const float* x     = (const float*)d_in[0];
    const float* ln1_g = (const float*)d_in[1];
    const float* ln1_b = (const float*)d_in[2];
    const float* w_qkv = (const float*)d_in[3];
    const float* w_out = (const float*)d_in[4];
    const float* b_out = (const float*)d_in[5];
    const float* res_w = (const float*)d_in[6];
    const float* ln2_g = (const float*)d_in[7];
    const float* ln2_b = (const float*)d_in[8];
    const float* w1    = (const float*)d_in[9];
    const float* b1    = (const float*)d_in[10];
    const float* w2    = (const float*)d_in[11];
    const float* b2    = (const float*)d_in[12];

    float *Y,*XN,*QKV,*Q,*K,*V,*QL,*KL,*X2,*A1,*A3,*A2,*Zb,*Z2,*XZ,*T1,*T2,*A3V,*P,*OH,*ONBD,*HID;
    cudaGetSymbolAddress((void**)&Y,   g_Y);
    cudaGetSymbolAddress((void**)&XN,  g_XN);
    cudaGetSymbolAddress((void**)&QKV, g_QKV);
    cudaGetSymbolAddress((void**)&Q,   g_Q);
    cudaGetSymbolAddress((void**)&K,   g_K);
    cudaGetSymbolAddress((void**)&V,   g_V);
    cudaGetSymbolAddress((void**)&QL,  g_QL);
    cudaGetSymbolAddress((void**)&KL,  g_KL);
    cudaGetSymbolAddress((void**)&X2,  g_X2);
    cudaGetSymbolAddress((void**)&A1,  g_A1);
    cudaGetSymbolAddress((void**)&A3,  g_A3);
    cudaGetSymbolAddress((void**)&A2,  g_A2);
    cudaGetSymbolAddress((void**)&Zb,  g_Zb);
    cudaGetSymbolAddress((void**)&Z2,  g_Z2);
    cudaGetSymbolAddress((void**)&XZ,  g_XZ);
    cudaGetSymbolAddress((void**)&T1,  g_T1);
    cudaGetSymbolAddress((void**)&T2,  g_T2);
    cudaGetSymbolAddress((void**)&A3V, g_A3V);
    cudaGetSymbolAddress((void**)&P,   g_P);
    cudaGetSymbolAddress((void**)&OH,  g_OH);
    cudaGetSymbolAddress((void**)&ONBD,g_ONBD);
    cudaGetSymbolAddress((void**)&HID, g_HID);

    cudaMemcpyAsync(Y, x, sizeof(float)*(size_t)CB*CN*CD, cudaMemcpyDeviceToDevice);

    const long long MM  = (long long)CML*CML;
    const long long SXD = (long long)CML*CDH;
    const long long SBH = (long long)CBH*SXD;

    for (int blk = 0; blk < 2; blk++) {
        const float* p_ln1g = ln1_g + blk*CD;
        const float* p_ln1b = ln1_b + blk*CD;
        const float* p_wqkv = w_qkv + (long long)blk*CD*3*CINNER;
        const float* p_wout = w_out + (long long)blk*CINNER*CD;
        const float* p_bout = b_out + blk*CD;
        const float* p_resw = res_w + blk*CH*33;
        const float* p_ln2g = ln2_g + blk*CD;
        const float* p_ln2b = ln2_b + blk*CD;
        const float* p_w1   = w1 + (long long)blk*CD*2*CD;
        const float* p_b1   = b1 + blk*2*CD;
        const float* p_w2   = w2 + (long long)blk*2*CD*CD;
        const float* p_b2   = b2 + blk*CD;

        layernorm_kernel<<<CB*CN, 256>>>(Y, p_ln1g, p_ln1b, XN);

        // QKV = XN @ w_qkv  [16384, 768]
        gemm128_kernel<0><<<dim3(6, 128), 256>>>(XN, p_wqkv, QKV, nullptr,
            CB*CN, 3*CINNER, CD, 0, 0, 0, 0.f, nullptr, nullptr);

        split_heads_kernel<<<(CB*CH*CN*CDH)/256, 256>>>(QKV, Q, K, V);
        landmark_kernel<<<(CBH*CML*CDH)/256, 256>>>(Q, K, QL, KL);

        // attn1 = softmax(Q @ KL^T)  [bh][4096, 256]
        gemmT_kernel<<<dim3(4, 64, CBH), 256>>>(Q, KL, A1,
            CN, CML, CDH, (long long)CN*CDH, SXD, (long long)CN*CML);
        softmax256_kernel<<<(CBH*CN)/8, 256>>>(A1);

        // attn2 = softmax(QL @ KL^T) [bh][256, 256]
        gemmT_kernel<<<dim3(4, 4, CBH), 256>>>(QL, KL, A2,
            CML, CML, CDH, SXD, SXD, MM);
        softmax256_kernel<<<(CBH*CML)/8, 256>>>(A2);

        // attn3 = softmax(QL @ K^T)  [bh][256, 4096]
        gemmT_kernel<<<dim3(64, 4, CBH), 256>>>(QL, K, A3,
            CML, CN, CDH, SXD, (long long)CN*CDH, (long long)CML*CN);
        softmax4096_kernel<<<CBH*CML, 256>>>(A3);

        // ---- Moore-Penrose pinv: 5 tf32 TC iterations + 1 fp32 cleanup ----
        zero_gmax_kernel<<<1, 1>>>();
        abs_rowsum_max_kernel<<<CBH*CML, 256>>>(A2);
        abs_colsum_max_kernel<<<CBH, 256>>>(A2);
        zinit_kernel<<<(int)((CBH*MM)/256), 256>>>(A2, Zb);

        float* zc = Zb; float* zn = Z2;
        for (int it = 0; it < 5; it++) {
            pinv_tc_kernel<3><<<dim3(2,2,CBH), 256>>>(A2, zc, XZ, T1, 7.0f);
            pinv_tc_kernel<1><<<dim3(2,2,CBH), 256>>>(XZ, T1, T2, nullptr, 15.0f);
            pinv_tc_kernel<1><<<dim3(2,2,CBH), 256>>>(XZ, T2, T1, nullptr, 13.0f);
            pinv_tc_kernel<2><<<dim3(2,2,CBH), 256>>>(zc, T1, zn, nullptr, 0.25f);
            float* t = zc; zc = zn; zn = t;
        }
        // final iteration in fp32 (cubic contraction wipes tf32 noise)
        gemm128_kernel<3><<<dim3(2,2,CBH), 256>>>(A2, zc, XZ, T1,
            CML, CML, CML, MM, MM, MM, 7.0f, nullptr, nullptr);
        gemm128_kernel<1><<<dim3(2,2,CBH), 256>>>(XZ, T1, T2, nullptr,
            CML, CML, CML, MM, MM, MM, 15.0f, nullptr, nullptr);
        gemm128_kernel<1><<<dim3(2,2,CBH), 256>>>(XZ, T2, T1, nullptr,
            CML, CML, CML, MM, MM, MM, 13.0f, nullptr, nullptr);
        gemm128_kernel<2><<<dim3(2,2,CBH), 256>>>(zc, T1, zn, nullptr,
            CML, CML, CML, MM, MM, MM, 0.25f, nullptr, nullptr);
        { float* t = zc; zc = zn; zn = t; }

        // X1 = attn3 @ V  [bh][256,32] via deterministic split-K(8)
        gemm_n32_kernel<64, 8><<<dim3(4, 8, CBH), 128>>>(A3, V, P,
            CML, CN, (long long)CML*CN, (long long)CN*CDH, SXD, SBH);
        reduce8_kernel<<<(int)(SBH/256), 256>>>(P, A3V);

        // X2 = pinv @ X1  [bh][256,32]
        gemm_n32_kernel<64, 1><<<dim3(4, 1, CBH), 128>>>(zc, A3V, X2,
            CML, CML, MM, SXD, SXD, 0);

        // OH = attn1 @ X2  [bh][4096,32]  (chain reorder: replaces 17 GF GEMM)
        gemm_n32_kernel<128, 1><<<dim3(32, 1, CBH), 256>>>(A1, X2, OH,
            CN, CML, (long long)CN*CML, SXD, (long long)CN*CDH, 0);

        // OH += depthwise conv(V), merge heads
        conv_add_kernel<<<(CB*CH*CN*CDH)/256, 256>>>(V, p_resw, OH);
        merge_heads_kernel<<<(CB*CN*CD)/256, 256>>>(OH, ONBD);

        // Y = Y + ONBD @ w_out + b_out
        gemm128_kernel<4><<<dim3(2, 128), 256>>>(ONBD, p_wout, Y, nullptr,
            CB*CN, CD, CINNER, 0, 0, 0, 0.f, p_bout, Y);

        // MLP
        layernorm_kernel<<<CB*CN, 256>>>(Y, p_ln2g, p_ln2b, XN);
        gemm128_kernel<5><<<dim3(4, 128), 256>>>(XN, p_w1, HID, nullptr,
            CB*CN, 2*CD, CD, 0, 0, 0, 0.f, p_b1, nullptr);
        gemm128_kernel<4><<<dim3(2, 128), 256>>>(HID, p_w2, Y, nullptr,
            CB*CN, CD, 2*CD, 0, 0, 0, 0.f, p_b2, Y);
    }

    cudaMemcpyAsync(d_out, Y, sizeof(float)*(size_t)CB*CN*CD, cudaMemcpyDeviceToDevice);
}

// round 5
// speedup vs baseline: 2.2548x; 1.2078x over previous
#include <cuda_runtime.h>
#include <math.h>

#define CB 4
#define CN 4096
#define CD 256
#define CH 8
#define CDH 32
#define CML 256
#define CBH (CB*CH)
#define CINNER 256

// ---------------- scratch ----------------------------------------------------
__device__ float g_Y   [CB*CN*CD];
__device__ float g_XN  [CB*CN*CD];
__device__ float g_QKV [CB*CN*3*CD];
__device__ float g_Q   [CB*CH*CN*CDH];
__device__ float g_K   [CB*CH*CN*CDH];
__device__ float g_V   [CB*CH*CN*CDH];
__device__ float g_QL  [CBH*CML*CDH];
__device__ float g_KL  [CBH*CML*CDH];
__device__ float g_X2  [CBH*CML*CDH];
__device__ float g_A1  [(long long)CBH*CN*CML];
__device__ float g_A3  [(long long)CBH*CML*CN];
__device__ float g_A2  [CBH*CML*CML];
__device__ float g_Zb  [CBH*CML*CML];
__device__ float g_Z2  [CBH*CML*CML];
__device__ float g_XZ  [CBH*CML*CML];
__device__ float g_T1  [CBH*CML*CML];
__device__ float g_T2  [CBH*CML*CML];
__device__ float g_A3V [CBH*CML*CDH];
__device__ float g_P   [8*CBH*CML*CDH];
__device__ float g_OH  [CB*CH*CN*CDH];
__device__ float g_ONBD[CB*CN*CD];
__device__ float g_HID [CB*CN*2*CD];
__device__ float g_gmax1, g_gmax2;

__device__ __forceinline__ unsigned f2tf(float x) {
    unsigned u;
    asm("cvt.rna.tf32.f32 %0, %1;" : "=r"(u) : "f"(x));
    return u;
}

__device__ __forceinline__ void mma_tf32(float* c, unsigned a0, unsigned a1,
                                         unsigned a2, unsigned a3,
                                         unsigned b0, unsigned b1) {
    asm volatile(
        "mma.sync.aligned.m16n8k8.row.col.f32.tf32.tf32.f32 "
        "{%0,%1,%2,%3}, {%4,%5,%6,%7}, {%8,%9}, {%0,%1,%2,%3};"
        : "+f"(c[0]), "+f"(c[1]), "+f"(c[2]), "+f"(c[3])
        : "r"(a0), "r"(a1), "r"(a2), "r"(a3), "r"(b0), "r"(b1));
}

// ---------------- layernorm --------------------------------------------------
__global__ void layernorm_kernel(const float* __restrict__ x,
                                 const float* __restrict__ g,
                                 const float* __restrict__ b,
                                 float* __restrict__ out) {
    __shared__ float s[256];
    long long row = blockIdx.x;
    int tid = threadIdx.x;
    float v = x[row*CD + tid];
    s[tid] = v; __syncthreads();
    for (int o = 128; o > 0; o >>= 1) { if (tid < o) s[tid] += s[tid+o]; __syncthreads(); }
    float mu = s[0] * (1.0f/CD);
    __syncthreads();
    float d = v - mu;
    s[tid] = d*d; __syncthreads();
    for (int o = 128; o > 0; o >>= 1) { if (tid < o) s[tid] += s[tid+o]; __syncthreads(); }
    float inv = rsqrtf(s[0]*(1.0f/CD) + 1e-5f);
    out[row*CD + tid] = d * inv * g[tid] + b[tid];
}

// ---------------- generic tf32 TC GEMM: 128x128 tiles, BK=32 -----------------
// A [M,K] row-major. TB=false: B [K,N] row-major; TB=true: B [N,K] row-major.
// EPI: 0 C=AB | 1 C=aI-AB | 2 C=a*AB | 3 C=AB,C2=aI-AB | 4 AB+bias+res | 5 gelu(AB+bias)
// Requires M%128==0, N%128==0, K%32==0.
template<int EPI, bool TB>
__global__ void __launch_bounds__(256) tc_gemm_kernel(
    const float* __restrict__ A, const float* __restrict__ B,
    float* __restrict__ C, float* __restrict__ C2,
    int M, int N, int K,
    long long sA, long long sB, long long sC,
    float alpha, const float* __restrict__ bias, const float* __restrict__ res)
{
    A += (long long)blockIdx.z * sA;
    B += (long long)blockIdx.z * sB;
    C += (long long)blockIdx.z * sC;
    if (EPI == 3) C2 += (long long)blockIdx.z * sC;

    int m0 = blockIdx.y*128, n0 = blockIdx.x*128;
    __shared__ unsigned As[32][132];
    __shared__ unsigned Bs[32][132];
    int t = threadIdx.x;
    int w = t >> 5, l = t & 31;
    int wm = (w >> 2)*64, wn = (w & 3)*32;
    int grp = l >> 2, qid = l & 3;
    float acc[4][4][4] = {};
    int ar  = t & 127;
    int akg = (t >> 7)*16;
    int bkr = t >> 3;
    int bn4 = (t & 7)*4;

    for (int k0 = 0; k0 < K; k0 += 32) {
        #pragma unroll
        for (int i = 0; i < 4; i++) {
            float4 v = *(const float4*)(A + (long long)(m0+ar)*K + k0 + akg + i*4);
            As[akg+i*4+0][ar]=f2tf(v.x); As[akg+i*4+1][ar]=f2tf(v.y);
            As[akg+i*4+2][ar]=f2tf(v.z); As[akg+i*4+3][ar]=f2tf(v.w);
        }
        if (!TB) {
            #pragma unroll
            for (int i = 0; i < 4; i++) {
                int n = bn4 + i*32;
                float4 v = *(const float4*)(B + (long long)(k0+bkr)*N + n0 + n);
                Bs[bkr][n+0]=f2tf(v.x); Bs[bkr][n+1]=f2tf(v.y);
                Bs[bkr][n+2]=f2tf(v.z); Bs[bkr][n+3]=f2tf(v.w);
            }
        } else {
            #pragma unroll
            for (int i = 0; i < 4; i++) {
                float4 v = *(const float4*)(B + (long long)(n0+ar)*K + k0 + akg + i*4);
                Bs[akg+i*4+0][ar]=f2tf(v.x); Bs[akg+i*4+1][ar]=f2tf(v.y);
                Bs[akg+i*4+2][ar]=f2tf(v.z); Bs[akg+i*4+3][ar]=f2tf(v.w);
            }
        }
        __syncthreads();
        #pragma unroll
        for (int ks = 0; ks < 4; ks++) {
            int kb = ks*8;
            unsigned af[4][4], bf[4][2];
            #pragma unroll
            for (int mi = 0; mi < 4; mi++) {
                int mb = wm + mi*16;
                af[mi][0] = As[kb+qid  ][mb+grp  ];
                af[mi][1] = As[kb+qid  ][mb+grp+8];
                af[mi][2] = As[kb+qid+4][mb+grp  ];
                af[mi][3] = As[kb+qid+4][mb+grp+8];
            }
            #pragma unroll
            for (int ni = 0; ni < 4; ni++) {
                int nb = wn + ni*8;
                bf[ni][0] = Bs[kb+qid  ][nb+grp];
                bf[ni][1] = Bs[kb+qid+4][nb+grp];
            }
            #pragma unroll
            for (int mi = 0; mi < 4; mi++)
                #pragma unroll
                for (int ni = 0; ni < 4; ni++)
                    mma_tf32(acc[mi][ni], af[mi][0], af[mi][1], af[mi][2], af[mi][3],
                             bf[ni][0], bf[ni][1]);
        }
        __syncthreads();
    }
    #pragma unroll
    for (int mi = 0; mi < 4; mi++)
        #pragma unroll
        for (int ni = 0; ni < 4; ni++)
            #pragma unroll
            for (int r = 0; r < 4; r++) {
                int gm = m0 + wm + mi*16 + grp + ((r >= 2) ? 8 : 0);
                int gn = n0 + wn + ni*8 + 2*qid + (r & 1);
                float v = acc[mi][ni][r];
                long long off = (long long)gm*N + gn;
                if (EPI == 1)      C[off] = ((gm==gn)?alpha:0.0f) - v;
                else if (EPI == 2) C[off] = alpha * v;
                else if (EPI == 4) C[off] = v + bias[gn] + res[off];
                else if (EPI == 5) { v += bias[gn]; C[off] = 0.5f*v*(1.0f + erff(v*0.70710678118654752f)); }
                else               C[off] = v;
                if (EPI == 3)      C2[off] = ((gm==gn)?alpha:0.0f) - v;
            }
}

// ---------------- narrow-N (N=32) tf32 TC GEMM, optional split-K -------------
// A [M,K] row-major, B [K,32] row-major. M%128==0, K%(32*KS)==0.
template<int KS>
__global__ void __launch_bounds__(256) tc_n32_kernel(
    const float* __restrict__ A, const float* __restrict__ B, float* __restrict__ C,
    int M, int K, long long sA, long long sB, long long sC, long long sSlice)
{
    A += (long long)blockIdx.z * sA;
    B += (long long)blockIdx.z * sB;
    C += (long long)blockIdx.z * sC + ((KS > 1) ? (long long)blockIdx.y * sSlice : 0);
    int klen = K / KS;
    int kbeg = blockIdx.y * klen;
    __shared__ unsigned As[32][132];
    __shared__ unsigned Bs[32][36];
    int t = threadIdx.x;
    int w = t >> 5, l = t & 31;
    int grp = l >> 2, qid = l & 3;
    int m0 = blockIdx.x*128;
    int ar  = t & 127;
    int akg = (t >> 7)*16;
    int bk = t >> 3, bn4 = (t & 7)*4;
    float acc[4][4] = {};

    for (int k0 = kbeg; k0 < kbeg + klen; k0 += 32) {
        #pragma unroll
        for (int i = 0; i < 4; i++) {
            float4 v = *(const float4*)(A + (long long)(m0+ar)*K + k0 + akg + i*4);
            As[akg+i*4+0][ar]=f2tf(v.x); As[akg+i*4+1][ar]=f2tf(v.y);
            As[akg+i*4+2][ar]=f2tf(v.z); As[akg+i*4+3][ar]=f2tf(v.w);
        }
        {
            float4 v = *(const float4*)(B + (long long)(k0+bk)*32 + bn4);
            Bs[bk][bn4+0]=f2tf(v.x); Bs[bk][bn4+1]=f2tf(v.y);
            Bs[bk][bn4+2]=f2tf(v.z); Bs[bk][bn4+3]=f2tf(v.w);
        }
        __syncthreads();
        #pragma unroll
        for (int ks = 0; ks < 4; ks++) {
            int kb = ks*8;
            int mb = w*16;
            unsigned a0 = As[kb+qid  ][mb+grp  ];
            unsigned a1 = As[kb+qid  ][mb+grp+8];
            unsigned a2 = As[kb+qid+4][mb+grp  ];
            unsigned a3 = As[kb+qid+4][mb+grp+8];
            #pragma unroll
            for (int ni = 0; ni < 4; ni++) {
                unsigned b0 = Bs[kb+qid  ][ni*8+grp];
                unsigned b1 = Bs[kb+qid+4][ni*8+grp];
                mma_tf32(acc[ni], a0, a1, a2, a3, b0, b1);
            }
        }
        __syncthreads();
    }
    #pragma unroll
    for (int ni = 0; ni < 4; ni++)
        #pragma unroll
        for (int r = 0; r < 4; r++) {
            int gm = m0 + w*16 + grp + ((r >= 2) ? 8 : 0);
            int gn = ni*8 + 2*qid + (r & 1);
            C[(long long)gm*32 + gn] = acc[ni][r];
        }
}

__global__ void reduce8_kernel(const float* __restrict__ P, float* __restrict__ out) {
    long long j = (long long)blockIdx.x*256 + threadIdx.x;
    const long long S = (long long)CBH*CML*CDH;
    float s = 0.f;
    #pragma unroll
    for (int i = 0; i < 8; i++) s += P[i*S + j];
    out[j] = s;
}

// ---------------- single-pass softmaxes --------------------------------------
__global__ void softmax256_kernel(float* __restrict__ x) {
    long long row = (long long)blockIdx.x*8 + (threadIdx.x >> 5);
    int lane = threadIdx.x & 31;
    float* p = x + row*256;
    float4 a = *(float4*)(p + lane*4);
    float4 b = *(float4*)(p + 128 + lane*4);
    float m = fmaxf(fmaxf(fmaxf(a.x,a.y), fmaxf(a.z,a.w)),
                    fmaxf(fmaxf(b.x,b.y), fmaxf(b.z,b.w)));
    #pragma unroll
    for (int o = 16; o > 0; o >>= 1) m = fmaxf(m, __shfl_xor_sync(0xffffffffu, m, o));
    a.x=__expf(a.x-m); a.y=__expf(a.y-m); a.z=__expf(a.z-m); a.w=__expf(a.w-m);
    b.x=__expf(b.x-m); b.y=__expf(b.y-m); b.z=__expf(b.z-m); b.w=__expf(b.w-m);
    float s = a.x+a.y+a.z+a.w + b.x+b.y+b.z+b.w;
    #pragma unroll
    for (int o = 16; o > 0; o >>= 1) s += __shfl_xor_sync(0xffffffffu, s, o);
    float inv = 1.0f / s;
    a.x*=inv; a.y*=inv; a.z*=inv; a.w*=inv;
    b.x*=inv; b.y*=inv; b.z*=inv; b.w*=inv;
    *(float4*)(p + lane*4) = a;
    *(float4*)(p + 128 + lane*4) = b;
}

__global__ void softmax4096_kernel(float* __restrict__ x) {
    long long row = blockIdx.x;
    float* p = x + row*4096;
    int t = threadIdx.x;
    __shared__ float red[8];
    float4 v[4];
    #pragma unroll
    for (int i = 0; i < 4; i++) v[i] = *(float4*)(p + t*4 + i*1024);
    float m = -3.4e38f;
    #pragma unroll
    for (int i = 0; i < 4; i++)
        m = fmaxf(m, fmaxf(fmaxf(v[i].x, v[i].y), fmaxf(v[i].z, v[i].w)));
    #pragma unroll
    for (int o = 16; o > 0; o >>= 1) m = fmaxf(m, __shfl_xor_sync(0xffffffffu, m, o));
    if ((t & 31) == 0) red[t >> 5] = m;
    __syncthreads();
    m = red[0];
    #pragma unroll
    for (int i = 1; i < 8; i++) m = fmaxf(m, red[i]);
    float s = 0.f;
    #pragma unroll
    for (int i = 0; i < 4; i++) {
        v[i].x = __expf(v[i].x - m); v[i].y = __expf(v[i].y - m);
        v[i].z = __expf(v[i].z - m); v[i].w = __expf(v[i].w - m);
        s += v[i].x + v[i].y + v[i].z + v[i].w;
    }
    #pragma unroll
    for (int o = 16; o > 0; o >>= 1) s += __shfl_xor_sync(0xffffffffu, s, o);
    __syncthreads();
    if ((t & 31) == 0) red[t >> 5] = s;
    __syncthreads();
    s = 0.f;
    #pragma unroll
    for (int i = 0; i < 8; i++) s += red[i];
    float inv = 1.0f / s;
    #pragma unroll
    for (int i = 0; i < 4; i++) {
        v[i].x *= inv; v[i].y *= inv; v[i].z *= inv; v[i].w *= inv;
        *(float4*)(p + t*4 + i*1024) = v[i];
    }
}

// ---------------- misc elementwise -------------------------------------------
__global__ void split_heads_kernel(const float* __restrict__ qkv,
                                   float* __restrict__ q, float* __restrict__ k,
                                   float* __restrict__ v) {
    long long idx = (long long)blockIdx.x*256 + threadIdx.x;
    int d = idx & 31;
    long long t = idx >> 5;
    int n = (int)(t & (CN-1));
    t >>= 12;
    int h = (int)(t & 7);
    int b = (int)(t >> 3);
    long long src = ((long long)b*CN + n)*(3*CINNER) + h*CDH + d;
    q[idx] = qkv[src] * 0.17677669529663687f;
    k[idx] = qkv[src + CINNER];
    v[idx] = qkv[src + 2*CINNER];
}

__global__ void landmark_kernel(const float* __restrict__ q, const float* __restrict__ k,
                                float* __restrict__ ql, float* __restrict__ kl) {
    long long idx = (long long)blockIdx.x*256 + threadIdx.x;
    int d = idx & 31;
    long long t = idx >> 5;
    int m = (int)(t & (CML-1));
    long long bh = t >> 8;
    long long base = (bh*CN + (long long)m*16)*CDH + d;
    float sq = 0.f, sk = 0.f;
    #pragma unroll
    for (int j = 0; j < 16; j++) { sq += q[base + j*CDH]; sk += k[base + j*CDH]; }
    ql[idx] = sq * 0.0625f;
    kl[idx] = sk * 0.0625f;
}

// ---------------- pinv scale (GLOBAL max across B,H) -------------------------
__global__ void zero_gmax_kernel() { g_gmax1 = 0.f; g_gmax2 = 0.f; }

__global__ void abs_rowsum_max_kernel(const float* __restrict__ x) {
    __shared__ float s[256];
    long long row = blockIdx.x;
    int tid = threadIdx.x;
    float v = fabsf(x[row*CML + tid]);
    s[tid] = v; __syncthreads();
    for (int o = 128; o > 0; o >>= 1) { if (tid < o) s[tid] += s[tid+o]; __syncthreads(); }
    if (tid == 0) atomicMax((int*)&g_gmax1, __float_as_int(s[0]));
}

__global__ void abs_colsum_max_kernel(const float* __restrict__ x) {
    const float* p = x + (long long)blockIdx.x*CML*CML;
    int j = threadIdx.x;
    float s = 0.f;
    for (int i = 0; i < CML; i++) s += fabsf(p[i*CML + j]);
    atomicMax((int*)&g_gmax2, __float_as_int(s));
}

__global__ void zinit_kernel(const float* __restrict__ x, float* __restrict__ z) {
    long long idx = (long long)blockIdx.x*256 + threadIdx.x;
    int j = (int)(idx & 255);
    int i = (int)((idx >> 8) & 255);
    long long bh = idx >> 16;
    float denom = g_gmax1 * g_gmax2;
    z[idx] = x[(bh << 16) + ((long long)j << 8) + i] / denom;
}

// ---------------- depthwise conv (k=33, pad=16) + merge ----------------------
__global__ void conv_add_kernel(const float* __restrict__ v, const float* __restrict__ w,
                                float* __restrict__ oh) {
    long long idx = (long long)blockIdx.x*256 + threadIdx.x;
    int d = (int)(idx & 31);
    long long t = idx >> 5;
    int n = (int)(t & (CN-1));
    long long bh = t >> 12;
    int h = (int)(bh & 7);
    const float* wp = w + h*33;
    const float* vp = v + bh*(long long)CN*CDH + d;
    float s = 0.f;
    #pragma unroll
    for (int tt = 0; tt < 33; tt++) {
        int nn = n + tt - 16;
        if (nn >= 0 && nn < CN) s += vp[(long long)nn*CDH] * wp[tt];
    }
    oh[idx] += s;
}

__global__ void merge_heads_kernel(const float* __restrict__ oh, float* __restrict__ out) {
    long long idx = (long long)blockIdx.x*256 + threadIdx.x;
    int d = (int)(idx & 31);
    long long t = idx >> 5;
    int h = (int)(t & 7);
    t >>= 3;
    int n = (int)(t & (CN-1));
    int b = (int)(t >> 12);
    out[idx] = oh[((((long long)b*CH + h)*CN) + n)*CDH + d];
}

// ---------------- host orchestration -----------------------------------------
extern "C" void kernel_launch(void* const* d_in, const int* in_sizes, int n_in,
                              void* d_out, int out_size) {
    const float* x     = (const float*)d_in[0];
    const float* ln1_g = (const float*)d_in[1];
    const float* ln1_b = (const float*)d_in[2];
    const float* w_qkv = (const float*)d_in[3];
    const float* w_out = (const float*)d_in[4];
    const float* b_out = (const float*)d_in[5];
    const float* res_w = (const float*)d_in[6];
    const float* ln2_g = (const float*)d_in[7];
    const float* ln2_b = (const float*)d_in[8];
    const float* w1    = (const float*)d_in[9];
    const float* b1    = (const float*)d_in[10];
    const float* w2    = (const float*)d_in[11];
    const float* b2    = (const float*)d_in[12];

    float *Y,*XN,*QKV,*Q,*K,*V,*QL,*KL,*X2,*A1,*A3,*A2,*Zb,*Z2,*XZ,*T1,*T2,*A3V,*P,*OH,*ONBD,*HID;
    cudaGetSymbolAddress((void**)&Y,   g_Y);
    cudaGetSymbolAddress((void**)&XN,  g_XN);
    cudaGetSymbolAddress((void**)&QKV, g_QKV);
    cudaGetSymbolAddress((void**)&Q,   g_Q);
    cudaGetSymbolAddress((void**)&K,   g_K);
    cudaGetSymbolAddress((void**)&V,   g_V);
    cudaGetSymbolAddress((void**)&QL,  g_QL);
    cudaGetSymbolAddress((void**)&KL,  g_KL);
    cudaGetSymbolAddress((void**)&X2,  g_X2);
    cudaGetSymbolAddress((void**)&A1,  g_A1);
    cudaGetSymbolAddress((void**)&A3,  g_A3);
    cudaGetSymbolAddress((void**)&A2,  g_A2);
    cudaGetSymbolAddress((void**)&Zb,  g_Zb);
    cudaGetSymbolAddress((void**)&Z2,  g_Z2);
    cudaGetSymbolAddress((void**)&XZ,  g_XZ);
    cudaGetSymbolAddress((void**)&T1,  g_T1);
    cudaGetSymbolAddress((void**)&T2,  g_T2);
    cudaGetSymbolAddress((void**)&A3V, g_A3V);
    cudaGetSymbolAddress((void**)&P,   g_P);
    cudaGetSymbolAddress((void**)&OH,  g_OH);
    cudaGetSymbolAddress((void**)&ONBD,g_ONBD);
    cudaGetSymbolAddress((void**)&HID, g_HID);

    cudaMemcpyAsync(Y, x, sizeof(float)*(size_t)CB*CN*CD, cudaMemcpyDeviceToDevice);

    const long long MM  = (long long)CML*CML;
    const long long SXD = (long long)CML*CDH;
    const long long SBH = (long long)CBH*SXD;

    for (int blk = 0; blk < 2; blk++) {
        const float* p_ln1g = ln1_g + blk*CD;
        const float* p_ln1b = ln1_b + blk*CD;
        const float* p_wqkv = w_qkv + (long long)blk*CD*3*CINNER;
        const float* p_wout = w_out + (long long)blk*CINNER*CD;
        const float* p_bout = b_out + blk*CD;
        const float* p_resw = res_w + blk*CH*33;
        const float* p_ln2g = ln2_g + blk*CD;
        const float* p_ln2b = ln2_b + blk*CD;
        const float* p_w1   = w1 + (long long)blk*CD*2*CD;
        const float* p_b1   = b1 + blk*2*CD;
        const float* p_w2   = w2 + (long long)blk*2*CD*CD;
        const float* p_b2   = b2 + blk*CD;

        layernorm_kernel<<<CB*CN, 256>>>(Y, p_ln1g, p_ln1b, XN);

        // QKV = XN @ w_qkv  [16384, 768] K=256
        tc_gemm_kernel<0,false><<<dim3(6, 128), 256>>>(XN, p_wqkv, QKV, nullptr,
            CB*CN, 3*CINNER, CD, 0, 0, 0, 0.f, nullptr, nullptr);

        split_heads_kernel<<<(CB*CH*CN*CDH)/256, 256>>>(QKV, Q, K, V);
        landmark_kernel<<<(CBH*CML*CDH)/256, 256>>>(Q, K, QL, KL);

        // attn1 = softmax(Q @ KL^T)  [bh][4096, 256] K=32
        tc_gemm_kernel<0,true><<<dim3(2, 32, CBH), 256>>>(Q, KL, A1, nullptr,
            CN, CML, CDH, (long long)CN*CDH, SXD, (long long)CN*CML, 0.f, nullptr, nullptr);
        softmax256_kernel<<<(CBH*CN)/8, 256>>>(A1);

        // attn2 = softmax(QL @ KL^T) [bh][256, 256] K=32
        tc_gemm_kernel<0,true><<<dim3(2, 2, CBH), 256>>>(QL, KL, A2, nullptr,
            CML, CML, CDH, SXD, SXD, MM, 0.f, nullptr, nullptr);
        softmax256_kernel<<<(CBH*CML)/8, 256>>>(A2);

        // attn3 = softmax(QL @ K^T)  [bh][256, 4096] K=32
        tc_gemm_kernel<0,true><<<dim3(32, 2, CBH), 256>>>(QL, K, A3, nullptr,
            CML, CN, CDH, SXD, (long long)CN*CDH, (long long)CML*CN, 0.f, nullptr, nullptr);
        softmax4096_kernel<<<CBH*CML, 256>>>(A3);

        // ---- Moore-Penrose pinv: 6 tf32 TC iterations ----
        zero_gmax_kernel<<<1, 1>>>();
        abs_rowsum_max_kernel<<<CBH*CML, 256>>>(A2);
        abs_colsum_max_kernel<<<CBH, 256>>>(A2);
        zinit_kernel<<<(int)((CBH*MM)/256), 256>>>(A2, Zb);

        float* zc = Zb; float* zn = Z2;
        for (int it = 0; it < 6; it++) {
            tc_gemm_kernel<3,false><<<dim3(2,2,CBH), 256>>>(A2, zc, XZ, T1,
                CML, CML, CML, MM, MM, MM, 7.0f, nullptr, nullptr);
            tc_gemm_kernel<1,false><<<dim3(2,2,CBH), 256>>>(XZ, T1, T2, nullptr,
                CML, CML, CML, MM, MM, MM, 15.0f, nullptr, nullptr);
            tc_gemm_kernel<1,false><<<dim3(2,2,CBH), 256>>>(XZ, T2, T1, nullptr,
                CML, CML, CML, MM, MM, MM, 13.0f, nullptr, nullptr);
            tc_gemm_kernel<2,false><<<dim3(2,2,CBH), 256>>>(zc, T1, zn, nullptr,
                CML, CML, CML, MM, MM, MM, 0.25f, nullptr, nullptr);
            float* t = zc; zc = zn; zn = t;
        }

        // X1 = attn3 @ V  [bh][256,32] K=4096, deterministic split-K(8)
        tc_n32_kernel<8><<<dim3(2, 8, CBH), 256>>>(A3, V, P,
            CML, CN, (long long)CML*CN, (long long)CN*CDH, SXD, SBH);
        reduce8_kernel<<<(int)(SBH/256), 256>>>(P, A3V);

        // X2 = pinv @ X1  [bh][256,32] K=256
        tc_n32_kernel<1><<<dim3(2, 1, CBH), 256>>>(zc, A3V, X2,
            CML, CML, MM, SXD, SXD, 0);

        // OH = attn1 @ X2  [bh][4096,32] K=256
        tc_n32_kernel<1><<<dim3(32, 1, CBH), 256>>>(A1, X2, OH,
            CN, CML, (long long)CN*CML, SXD, (long long)CN*CDH, 0);

        // OH += depthwise conv(V), merge heads
        conv_add_kernel<<<(CB*CH*CN*CDH)/256, 256>>>(V, p_resw, OH);
        merge_heads_kernel<<<(CB*CN*CD)/256, 256>>>(OH, ONBD);

        // Y = Y + ONBD @ w_out + b_out
        tc_gemm_kernel<4,false><<<dim3(2, 128), 256>>>(ONBD, p_wout, Y, nullptr,
            CB*CN, CD, CINNER, 0, 0, 0, 0.f, p_bout, Y);

        // MLP
        layernorm_kernel<<<CB*CN, 256>>>(Y, p_ln2g, p_ln2b, XN);
        tc_gemm_kernel<5,false><<<dim3(4, 128), 256>>>(XN, p_w1, HID, nullptr,
            CB*CN, 2*CD, CD, 0, 0, 0, 0.f, p_b1, nullptr);
        tc_gemm_kernel<4,false><<<dim3(2, 128), 256>>>(HID, p_w2, Y, nullptr,
            CB*CN, CD, 2*CD, 0, 0, 0, 0.f, p_b2, Y);
    }

    cudaMemcpyAsync(d_out, Y, sizeof(float)*(size_t)CB*CN*CD, cudaMemcpyDeviceToDevice);
}

// round 6
// speedup vs baseline: 2.8569x; 1.2670x over previous
#include <cuda_runtime.h>
#include <math.h>

#define CB 4
#define CN 4096
#define CD 256
#define CH 8
#define CDH 32
#define CML 256
#define CBH (CB*CH)
#define CINNER 256
#define FUSED_SMEM (256*36*4 + 128*40*4)   // 57344 bytes

// ---------------- scratch ----------------------------------------------------
__device__ float g_Y   [CB*CN*CD];
__device__ float g_XN  [CB*CN*CD];
__device__ float g_Q   [CB*CH*CN*CDH];
__device__ float g_K   [CB*CH*CN*CDH];
__device__ float g_V   [CB*CH*CN*CDH];
__device__ float g_QL  [CBH*CML*CDH];
__device__ float g_KL  [CBH*CML*CDH];
__device__ float g_X2  [CBH*CML*CDH];
__device__ float g_A2  [CBH*CML*CML];
__device__ float g_Zb  [CBH*CML*CML];
__device__ float g_Z2  [CBH*CML*CML];
__device__ float g_XZ  [CBH*CML*CML];
__device__ float g_T1  [CBH*CML*CML];
__device__ float g_T2  [CBH*CML*CML];
__device__ float g_X1  [CBH*CML*CDH];
__device__ float g_OH  [CB*CH*CN*CDH];
__device__ float g_ONBD[CB*CN*CD];
__device__ float g_HID [CB*CN*2*CD];
__device__ float g_gmax1, g_gmax2;

__device__ __forceinline__ unsigned f2tf(float x) {
    unsigned u;
    asm("cvt.rna.tf32.f32 %0, %1;" : "=r"(u) : "f"(x));
    return u;
}
__device__ __forceinline__ unsigned pack_bf16(float lo, float hi) {
    unsigned r;
    asm("cvt.rn.bf16x2.f32 %0, %1, %2;" : "=r"(r) : "f"(hi), "f"(lo));
    return r;
}
__device__ __forceinline__ void mma_tf32(float* c, unsigned a0, unsigned a1,
                                         unsigned a2, unsigned a3,
                                         unsigned b0, unsigned b1) {
    asm volatile(
        "mma.sync.aligned.m16n8k8.row.col.f32.tf32.tf32.f32 "
        "{%0,%1,%2,%3}, {%4,%5,%6,%7}, {%8,%9}, {%0,%1,%2,%3};"
        : "+f"(c[0]), "+f"(c[1]), "+f"(c[2]), "+f"(c[3])
        : "r"(a0), "r"(a1), "r"(a2), "r"(a3), "r"(b0), "r"(b1));
}
__device__ __forceinline__ void mma_bf16(float* c, unsigned a0, unsigned a1,
                                         unsigned a2, unsigned a3,
                                         unsigned b0, unsigned b1) {
    asm volatile(
        "mma.sync.aligned.m16n8k16.row.col.f32.bf16.bf16.f32 "
        "{%0,%1,%2,%3}, {%4,%5,%6,%7}, {%8,%9}, {%0,%1,%2,%3};"
        : "+f"(c[0]), "+f"(c[1]), "+f"(c[2]), "+f"(c[3])
        : "r"(a0), "r"(a1), "r"(a2), "r"(a3), "r"(b0), "r"(b1));
}

// ---------------- layernorm --------------------------------------------------
__global__ void layernorm_kernel(const float* __restrict__ x,
                                 const float* __restrict__ g,
                                 const float* __restrict__ b,
                                 float* __restrict__ out) {
    __shared__ float s[256];
    long long row = blockIdx.x;
    int tid = threadIdx.x;
    float v = x[row*CD + tid];
    s[tid] = v; __syncthreads();
    for (int o = 128; o > 0; o >>= 1) { if (tid < o) s[tid] += s[tid+o]; __syncthreads(); }
    float mu = s[0] * (1.0f/CD);
    __syncthreads();
    float d = v - mu;
    s[tid] = d*d; __syncthreads();
    for (int o = 128; o > 0; o >>= 1) { if (tid < o) s[tid] += s[tid+o]; __syncthreads(); }
    float inv = rsqrtf(s[0]*(1.0f/CD) + 1e-5f);
    out[row*CD + tid] = d * inv * g[tid] + b[tid];
}

// ---------------- tf32 TC GEMM 128x128, BK=32, register-prefetched -----------
// EPI: 0 C=AB | 1 aI-AB | 2 a*AB | 3 C=AB,C2=aI-AB | 4 AB+bias+res
//      5 gelu(AB+bias) | 6 qkv-split (C=Q scaled, C2=K, C3=V)
template<int EPI, bool TB>
__global__ void __launch_bounds__(256) tc_gemm_kernel(
    const float* __restrict__ A, const float* __restrict__ B,
    float* __restrict__ C, float* __restrict__ C2, float* __restrict__ C3,
    int M, int N, int K,
    long long sA, long long sB, long long sC,
    float alpha, const float* __restrict__ bias, const float* __restrict__ res)
{
    A += (long long)blockIdx.z * sA;
    B += (long long)blockIdx.z * sB;
    C += (long long)blockIdx.z * sC;
    if (EPI == 3) C2 += (long long)blockIdx.z * sC;

    int m0 = blockIdx.y*128, n0 = blockIdx.x*128;
    __shared__ unsigned As[32][132];
    __shared__ unsigned Bs[32][132];
    int t = threadIdx.x;
    int w = t >> 5, l = t & 31;
    int wm = (w >> 2)*64, wn = (w & 3)*32;
    int grp = l >> 2, qid = l & 3;
    float acc[4][4][4] = {};
    int ar  = t & 127;
    int akg = (t >> 7)*16;
    int bkr = t >> 3;
    int bn4 = (t & 7)*4;

    const float* Arow = A + (long long)(m0+ar)*K;
    const float* Brow = TB ? (B + (long long)(n0+ar)*K) : nullptr;

    float4 pa[4], pb[4];
    #pragma unroll
    for (int i = 0; i < 4; i++) pa[i] = *(const float4*)(Arow + akg + i*4);
    if (!TB) {
        #pragma unroll
        for (int i = 0; i < 4; i++)
            pb[i] = *(const float4*)(B + (long long)bkr*N + n0 + bn4 + i*32);
    } else {
        #pragma unroll
        for (int i = 0; i < 4; i++) pb[i] = *(const float4*)(Brow + akg + i*4);
    }

    for (int k0 = 0; k0 < K; k0 += 32) {
        #pragma unroll
        for (int i = 0; i < 4; i++) {
            As[akg+i*4+0][ar]=f2tf(pa[i].x); As[akg+i*4+1][ar]=f2tf(pa[i].y);
            As[akg+i*4+2][ar]=f2tf(pa[i].z); As[akg+i*4+3][ar]=f2tf(pa[i].w);
        }
        if (!TB) {
            #pragma unroll
            for (int i = 0; i < 4; i++) {
                int n = bn4 + i*32;
                Bs[bkr][n+0]=f2tf(pb[i].x); Bs[bkr][n+1]=f2tf(pb[i].y);
                Bs[bkr][n+2]=f2tf(pb[i].z); Bs[bkr][n+3]=f2tf(pb[i].w);
            }
        } else {
            #pragma unroll
            for (int i = 0; i < 4; i++) {
                Bs[akg+i*4+0][ar]=f2tf(pb[i].x); Bs[akg+i*4+1][ar]=f2tf(pb[i].y);
                Bs[akg+i*4+2][ar]=f2tf(pb[i].z); Bs[akg+i*4+3][ar]=f2tf(pb[i].w);
            }
        }
        __syncthreads();
        if (k0 + 32 < K) {
            int kn = k0 + 32;
            #pragma unroll
            for (int i = 0; i < 4; i++) pa[i] = *(const float4*)(Arow + kn + akg + i*4);
            if (!TB) {
                #pragma unroll
                for (int i = 0; i < 4; i++)
                    pb[i] = *(const float4*)(B + (long long)(kn+bkr)*N + n0 + bn4 + i*32);
            } else {
                #pragma unroll
                for (int i = 0; i < 4; i++) pb[i] = *(const float4*)(Brow + kn + akg + i*4);
            }
        }
        #pragma unroll
        for (int ks = 0; ks < 4; ks++) {
            int kb = ks*8;
            unsigned af[4][4], bf[4][2];
            #pragma unroll
            for (int mi = 0; mi < 4; mi++) {
                int mb = wm + mi*16;
                af[mi][0] = As[kb+qid  ][mb+grp  ];
                af[mi][1] = As[kb+qid  ][mb+grp+8];
                af[mi][2] = As[kb+qid+4][mb+grp  ];
                af[mi][3] = As[kb+qid+4][mb+grp+8];
            }
            #pragma unroll
            for (int ni = 0; ni < 4; ni++) {
                int nb = wn + ni*8;
                bf[ni][0] = Bs[kb+qid  ][nb+grp];
                bf[ni][1] = Bs[kb+qid+4][nb+grp];
            }
            #pragma unroll
            for (int mi = 0; mi < 4; mi++)
                #pragma unroll
                for (int ni = 0; ni < 4; ni++)
                    mma_tf32(acc[mi][ni], af[mi][0], af[mi][1], af[mi][2], af[mi][3],
                             bf[ni][0], bf[ni][1]);
        }
        __syncthreads();
    }
    #pragma unroll
    for (int mi = 0; mi < 4; mi++)
        #pragma unroll
        for (int ni = 0; ni < 4; ni++)
            #pragma unroll
            for (int r = 0; r < 4; r++) {
                int gm = m0 + wm + mi*16 + grp + ((r >= 2) ? 8 : 0);
                int gn = n0 + wn + ni*8 + 2*qid + (r & 1);
                float v = acc[mi][ni][r];
                long long off = (long long)gm*N + gn;
                if (EPI == 6) {
                    int which = gn >> 8;
                    int h = (gn >> 5) & 7;
                    int d = gn & 31;
                    int b = gm >> 12;
                    int n_tok = gm & 4095;
                    long long dst = ((((long long)b*CH + h)*CN) + n_tok)*CDH + d;
                    if (which == 0)      C [dst] = v * 0.17677669529663687f;
                    else if (which == 1) C2[dst] = v;
                    else                 C3[dst] = v;
                    continue;
                }
                if (EPI == 1)      C[off] = ((gm==gn)?alpha:0.0f) - v;
                else if (EPI == 2) C[off] = alpha * v;
                else if (EPI == 4) C[off] = v + bias[gn] + res[off];
                else if (EPI == 5) { v += bias[gn]; C[off] = 0.5f*v*(1.0f + erff(v*0.70710678118654752f)); }
                else               C[off] = v;
                if (EPI == 3)      C2[off] = ((gm==gn)?alpha:0.0f) - v;
            }
}

// ---------------- fused attn1: OH = softmax(Q @ KL^T) @ X2 -------------------
// grid (32 chunks, CBH), 256 threads. smem dynamic FUSED_SMEM.
__global__ void __launch_bounds__(256) fused_attn1_kernel(
    const float* __restrict__ Q, const float* __restrict__ KL,
    const float* __restrict__ X2, float* __restrict__ OH)
{
    extern __shared__ unsigned smemu[];
    unsigned (*sKL)[36]  = (unsigned(*)[36])smemu;            // [n 256][k 32]+pad
    unsigned (*sX2p)[40] = (unsigned(*)[40])(smemu + 256*36); // [kh 128][n 32]+pad
    int bh = blockIdx.y;
    int m0 = blockIdx.x * 128;
    int t = threadIdx.x;
    int w = t >> 5, l = t & 31;
    int grp = l >> 2, qid = l & 3;
    const float* Qp  = Q  + ((long long)bh*CN + m0)*CDH;
    const float* KLp = KL + (long long)bh*CML*CDH;
    const float* Xp  = X2 + (long long)bh*CML*CDH;

    #pragma unroll
    for (int i = 0; i < 8; i++) {
        int e = t + i*256;
        int n = e >> 3, kq = (e & 7)*4;
        float4 v = *(const float4*)(KLp + n*32 + kq);
        sKL[n][kq+0]=f2tf(v.x); sKL[n][kq+1]=f2tf(v.y);
        sKL[n][kq+2]=f2tf(v.z); sKL[n][kq+3]=f2tf(v.w);
    }
    #pragma unroll
    for (int i = 0; i < 4; i++) {
        int e = t + i*256;
        int kh = e >> 3, nq = (e & 7)*4;
        float4 v0 = *(const float4*)(Xp + (2*kh  )*32 + nq);
        float4 v1 = *(const float4*)(Xp + (2*kh+1)*32 + nq);
        sX2p[kh][nq+0] = pack_bf16(v0.x, v1.x);
        sX2p[kh][nq+1] = pack_bf16(v0.y, v1.y);
        sX2p[kh][nq+2] = pack_bf16(v0.z, v1.z);
        sX2p[kh][nq+3] = pack_bf16(v0.w, v1.w);
    }
    __syncthreads();

    int mr = w*16;
    unsigned aq[4][4];
    #pragma unroll
    for (int ks = 0; ks < 4; ks++) {
        int k = ks*8;
        aq[ks][0] = f2tf(Qp[(mr+grp  )*32 + k+qid  ]);
        aq[ks][1] = f2tf(Qp[(mr+grp+8)*32 + k+qid  ]);
        aq[ks][2] = f2tf(Qp[(mr+grp  )*32 + k+qid+4]);
        aq[ks][3] = f2tf(Qp[(mr+grp+8)*32 + k+qid+4]);
    }
    float acc[32][4];
    #pragma unroll
    for (int ni = 0; ni < 32; ni++) { acc[ni][0]=0.f; acc[ni][1]=0.f; acc[ni][2]=0.f; acc[ni][3]=0.f; }
    #pragma unroll
    for (int ni = 0; ni < 32; ni++)
        #pragma unroll
        for (int ks = 0; ks < 4; ks++) {
            unsigned b0 = sKL[ni*8+grp][ks*8+qid];
            unsigned b1 = sKL[ni*8+grp][ks*8+qid+4];
            mma_tf32(acc[ni], aq[ks][0], aq[ks][1], aq[ks][2], aq[ks][3], b0, b1);
        }
    // softmax (rows mr+grp, mr+grp+8 — fully within qid-lane quad)
    float m1 = -3.4e38f, m2 = -3.4e38f;
    #pragma unroll
    for (int ni = 0; ni < 32; ni++) {
        m1 = fmaxf(m1, fmaxf(acc[ni][0], acc[ni][1]));
        m2 = fmaxf(m2, fmaxf(acc[ni][2], acc[ni][3]));
    }
    m1 = fmaxf(m1, __shfl_xor_sync(0xffffffffu, m1, 1));
    m1 = fmaxf(m1, __shfl_xor_sync(0xffffffffu, m1, 2));
    m2 = fmaxf(m2, __shfl_xor_sync(0xffffffffu, m2, 1));
    m2 = fmaxf(m2, __shfl_xor_sync(0xffffffffu, m2, 2));
    float s1 = 0.f, s2 = 0.f;
    #pragma unroll
    for (int ni = 0; ni < 32; ni++) {
        acc[ni][0] = __expf(acc[ni][0]-m1); acc[ni][1] = __expf(acc[ni][1]-m1);
        acc[ni][2] = __expf(acc[ni][2]-m2); acc[ni][3] = __expf(acc[ni][3]-m2);
        s1 += acc[ni][0] + acc[ni][1];
        s2 += acc[ni][2] + acc[ni][3];
    }
    s1 += __shfl_xor_sync(0xffffffffu, s1, 1);
    s1 += __shfl_xor_sync(0xffffffffu, s1, 2);
    s2 += __shfl_xor_sync(0xffffffffu, s2, 1);
    s2 += __shfl_xor_sync(0xffffffffu, s2, 2);
    float i1 = 1.0f/s1, i2 = 1.0f/s2;
    #pragma unroll
    for (int ni = 0; ni < 32; ni++) {
        acc[ni][0]*=i1; acc[ni][1]*=i1; acc[ni][2]*=i2; acc[ni][3]*=i2;
    }
    // P @ X2 (bf16)
    float ao[4][4] = {};
    #pragma unroll
    for (int c = 0; c < 16; c++) {
        unsigned a0 = pack_bf16(acc[2*c  ][0], acc[2*c  ][1]);
        unsigned a1 = pack_bf16(acc[2*c  ][2], acc[2*c  ][3]);
        unsigned a2 = pack_bf16(acc[2*c+1][0], acc[2*c+1][1]);
        unsigned a3 = pack_bf16(acc[2*c+1][2], acc[2*c+1][3]);
        #pragma unroll
        for (int j = 0; j < 4; j++) {
            unsigned b0 = sX2p[c*8+qid  ][j*8+grp];
            unsigned b1 = sX2p[c*8+qid+4][j*8+grp];
            mma_bf16(ao[j], a0, a1, a2, a3, b0, b1);
        }
    }
    float* Op = OH + ((long long)bh*CN + m0 + mr)*CDH;
    #pragma unroll
    for (int j = 0; j < 4; j++) {
        Op[(grp  )*32 + j*8+2*qid  ] = ao[j][0];
        Op[(grp  )*32 + j*8+2*qid+1] = ao[j][1];
        Op[(grp+8)*32 + j*8+2*qid  ] = ao[j][2];
        Op[(grp+8)*32 + j*8+2*qid+1] = ao[j][3];
    }
}

// ---------------- fused attn3: X1 = softmax(QL @ K^T) @ V (online) -----------
// grid (2, CBH), 256 threads. smem dynamic FUSED_SMEM.
__global__ void __launch_bounds__(256) fused_attn3_kernel(
    const float* __restrict__ QL, const float* __restrict__ Kg,
    const float* __restrict__ V, float* __restrict__ X1)
{
    extern __shared__ unsigned smemu[];
    unsigned (*sK)[36]  = (unsigned(*)[36])smemu;
    unsigned (*sVp)[40] = (unsigned(*)[40])(smemu + 256*36);
    int bh = blockIdx.y;
    int m0 = blockIdx.x * 128;
    int t = threadIdx.x;
    int w = t >> 5, l = t & 31;
    int grp = l >> 2, qid = l & 3;
    const float* Qp = QL + ((long long)bh*CML + m0)*CDH;

    int mr = w*16;
    unsigned aq[4][4];
    #pragma unroll
    for (int ks = 0; ks < 4; ks++) {
        int k = ks*8;
        aq[ks][0] = f2tf(Qp[(mr+grp  )*32 + k+qid  ]);
        aq[ks][1] = f2tf(Qp[(mr+grp+8)*32 + k+qid  ]);
        aq[ks][2] = f2tf(Qp[(mr+grp  )*32 + k+qid+4]);
        aq[ks][3] = f2tf(Qp[(mr+grp+8)*32 + k+qid+4]);
    }
    float ao[4][4] = {};
    float m1 = -3.4e38f, m2 = -3.4e38f, l1 = 0.f, l2 = 0.f;

    for (int kc = 0; kc < 16; kc++) {
        __syncthreads();
        const float* Kp = Kg + ((long long)bh*CN + kc*256)*CDH;
        const float* Vp = V  + ((long long)bh*CN + kc*256)*CDH;
        #pragma unroll
        for (int i = 0; i < 8; i++) {
            int e = t + i*256;
            int n = e >> 3, kq = (e & 7)*4;
            float4 v = *(const float4*)(Kp + n*32 + kq);
            sK[n][kq+0]=f2tf(v.x); sK[n][kq+1]=f2tf(v.y);
            sK[n][kq+2]=f2tf(v.z); sK[n][kq+3]=f2tf(v.w);
        }
        #pragma unroll
        for (int i = 0; i < 4; i++) {
            int e = t + i*256;
            int kh = e >> 3, nq = (e & 7)*4;
            float4 v0 = *(const float4*)(Vp + (2*kh  )*32 + nq);
            float4 v1 = *(const float4*)(Vp + (2*kh+1)*32 + nq);
            sVp[kh][nq+0] = pack_bf16(v0.x, v1.x);
            sVp[kh][nq+1] = pack_bf16(v0.y, v1.y);
            sVp[kh][nq+2] = pack_bf16(v0.z, v1.z);
            sVp[kh][nq+3] = pack_bf16(v0.w, v1.w);
        }
        __syncthreads();
        float acc[32][4];
        #pragma unroll
        for (int ni = 0; ni < 32; ni++) { acc[ni][0]=0.f; acc[ni][1]=0.f; acc[ni][2]=0.f; acc[ni][3]=0.f; }
        #pragma unroll
        for (int ni = 0; ni < 32; ni++)
            #pragma unroll
            for (int ks = 0; ks < 4; ks++) {
                unsigned b0 = sK[ni*8+grp][ks*8+qid];
                unsigned b1 = sK[ni*8+grp][ks*8+qid+4];
                mma_tf32(acc[ni], aq[ks][0], aq[ks][1], aq[ks][2], aq[ks][3], b0, b1);
            }
        float c1 = -3.4e38f, c2 = -3.4e38f;
        #pragma unroll
        for (int ni = 0; ni < 32; ni++) {
            c1 = fmaxf(c1, fmaxf(acc[ni][0], acc[ni][1]));
            c2 = fmaxf(c2, fmaxf(acc[ni][2], acc[ni][3]));
        }
        c1 = fmaxf(c1, __shfl_xor_sync(0xffffffffu, c1, 1));
        c1 = fmaxf(c1, __shfl_xor_sync(0xffffffffu, c1, 2));
        c2 = fmaxf(c2, __shfl_xor_sync(0xffffffffu, c2, 1));
        c2 = fmaxf(c2, __shfl_xor_sync(0xffffffffu, c2, 2));
        float n1 = fmaxf(m1, c1), n2 = fmaxf(m2, c2);
        float sc1 = __expf(m1 - n1), sc2 = __expf(m2 - n2);
        float s1 = 0.f, s2 = 0.f;
        #pragma unroll
        for (int ni = 0; ni < 32; ni++) {
            acc[ni][0] = __expf(acc[ni][0]-n1); acc[ni][1] = __expf(acc[ni][1]-n1);
            acc[ni][2] = __expf(acc[ni][2]-n2); acc[ni][3] = __expf(acc[ni][3]-n2);
            s1 += acc[ni][0] + acc[ni][1];
            s2 += acc[ni][2] + acc[ni][3];
        }
        s1 += __shfl_xor_sync(0xffffffffu, s1, 1);
        s1 += __shfl_xor_sync(0xffffffffu, s1, 2);
        s2 += __shfl_xor_sync(0xffffffffu, s2, 1);
        s2 += __shfl_xor_sync(0xffffffffu, s2, 2);
        l1 = l1*sc1 + s1; l2 = l2*sc2 + s2;
        m1 = n1; m2 = n2;
        #pragma unroll
        for (int j = 0; j < 4; j++) {
            ao[j][0]*=sc1; ao[j][1]*=sc1; ao[j][2]*=sc2; ao[j][3]*=sc2;
        }
        #pragma unroll
        for (int c = 0; c < 16; c++) {
            unsigned a0 = pack_bf16(acc[2*c  ][0], acc[2*c  ][1]);
            unsigned a1 = pack_bf16(acc[2*c  ][2], acc[2*c  ][3]);
            unsigned a2 = pack_bf16(acc[2*c+1][0], acc[2*c+1][1]);
            unsigned a3 = pack_bf16(acc[2*c+1][2], acc[2*c+1][3]);
            #pragma unroll
            for (int j = 0; j < 4; j++) {
                unsigned b0 = sVp[c*8+qid  ][j*8+grp];
                unsigned b1 = sVp[c*8+qid+4][j*8+grp];
                mma_bf16(ao[j], a0, a1, a2, a3, b0, b1);
            }
        }
    }
    float i1 = 1.0f/l1, i2 = 1.0f/l2;
    float* Op = X1 + ((long long)bh*CML + m0 + mr)*CDH;
    #pragma unroll
    for (int j = 0; j < 4; j++) {
        Op[(grp  )*32 + j*8+2*qid  ] = ao[j][0]*i1;
        Op[(grp  )*32 + j*8+2*qid+1] = ao[j][1]*i1;
        Op[(grp+8)*32 + j*8+2*qid  ] = ao[j][2]*i2;
        Op[(grp+8)*32 + j*8+2*qid+1] = ao[j][3]*i2;
    }
}

// ---------------- narrow-N (N=32) tf32 TC GEMM -------------------------------
__global__ void __launch_bounds__(256) tc_n32_kernel(
    const float* __restrict__ A, const float* __restrict__ B, float* __restrict__ C,
    int M, int K, long long sA, long long sB, long long sC)
{
    A += (long long)blockIdx.z * sA;
    B += (long long)blockIdx.z * sB;
    C += (long long)blockIdx.z * sC;
    __shared__ unsigned As[32][132];
    __shared__ unsigned Bs[32][36];
    int t = threadIdx.x;
    int w = t >> 5, l = t & 31;
    int grp = l >> 2, qid = l & 3;
    int m0 = blockIdx.x*128;
    int ar  = t & 127;
    int akg = (t >> 7)*16;
    int bk = t >> 3, bn4 = (t & 7)*4;
    float acc[4][4] = {};

    for (int k0 = 0; k0 < K; k0 += 32) {
        #pragma unroll
        for (int i = 0; i < 4; i++) {
            float4 v = *(const float4*)(A + (long long)(m0+ar)*K + k0 + akg + i*4);
            As[akg+i*4+0][ar]=f2tf(v.x); As[akg+i*4+1][ar]=f2tf(v.y);
            As[akg+i*4+2][ar]=f2tf(v.z); As[akg+i*4+3][ar]=f2tf(v.w);
        }
        {
            float4 v = *(const float4*)(B + (long long)(k0+bk)*32 + bn4);
            Bs[bk][bn4+0]=f2tf(v.x); Bs[bk][bn4+1]=f2tf(v.y);
            Bs[bk][bn4+2]=f2tf(v.z); Bs[bk][bn4+3]=f2tf(v.w);
        }
        __syncthreads();
        #pragma unroll
        for (int ks = 0; ks < 4; ks++) {
            int kb = ks*8;
            int mb = w*16;
            unsigned a0 = As[kb+qid  ][mb+grp  ];
            unsigned a1 = As[kb+qid  ][mb+grp+8];
            unsigned a2 = As[kb+qid+4][mb+grp  ];
            unsigned a3 = As[kb+qid+4][mb+grp+8];
            #pragma unroll
            for (int ni = 0; ni < 4; ni++) {
                unsigned b0 = Bs[kb+qid  ][ni*8+grp];
                unsigned b1 = Bs[kb+qid+4][ni*8+grp];
                mma_tf32(acc[ni], a0, a1, a2, a3, b0, b1);
            }
        }
        __syncthreads();
    }
    #pragma unroll
    for (int ni = 0; ni < 4; ni++)
        #pragma unroll
        for (int r = 0; r < 4; r++) {
            int gm = m0 + w*16 + grp + ((r >= 2) ? 8 : 0);
            int gn = ni*8 + 2*qid + (r & 1);
            C[(long long)gm*32 + gn] = acc[ni][r];
        }
}

// ---------------- softmax 256 ------------------------------------------------
__global__ void softmax256_kernel(float* __restrict__ x) {
    long long row = (long long)blockIdx.x*8 + (threadIdx.x >> 5);
    int lane = threadIdx.x & 31;
    float* p = x + row*256;
    float4 a = *(float4*)(p + lane*4);
    float4 b = *(float4*)(p + 128 + lane*4);
    float m = fmaxf(fmaxf(fmaxf(a.x,a.y), fmaxf(a.z,a.w)),
                    fmaxf(fmaxf(b.x,b.y), fmaxf(b.z,b.w)));
    #pragma unroll
    for (int o = 16; o > 0; o >>= 1) m = fmaxf(m, __shfl_xor_sync(0xffffffffu, m, o));
    a.x=__expf(a.x-m); a.y=__expf(a.y-m); a.z=__expf(a.z-m); a.w=__expf(a.w-m);
    b.x=__expf(b.x-m); b.y=__expf(b.y-m); b.z=__expf(b.z-m); b.w=__expf(b.w-m);
    float s = a.x+a.y+a.z+a.w + b.x+b.y+b.z+b.w;
    #pragma unroll
    for (int o = 16; o > 0; o >>= 1) s += __shfl_xor_sync(0xffffffffu, s, o);
    float inv = 1.0f / s;
    a.x*=inv; a.y*=inv; a.z*=inv; a.w*=inv;
    b.x*=inv; b.y*=inv; b.z*=inv; b.w*=inv;
    *(float4*)(p + lane*4) = a;
    *(float4*)(p + 128 + lane*4) = b;
}

// ---------------- misc -------------------------------------------------------
__global__ void landmark_kernel(const float* __restrict__ q, const float* __restrict__ k,
                                float* __restrict__ ql, float* __restrict__ kl) {
    long long idx = (long long)blockIdx.x*256 + threadIdx.x;
    int d = idx & 31;
    long long t = idx >> 5;
    int m = (int)(t & (CML-1));
    long long bh = t >> 8;
    long long base = (bh*CN + (long long)m*16)*CDH + d;
    float sq = 0.f, sk = 0.f;
    #pragma unroll
    for (int j = 0; j < 16; j++) { sq += q[base + j*CDH]; sk += k[base + j*CDH]; }
    ql[idx] = sq * 0.0625f;
    kl[idx] = sk * 0.0625f;
}

__global__ void zero_gmax_kernel() { g_gmax1 = 0.f; g_gmax2 = 0.f; }

__global__ void abs_rowsum_max_kernel(const float* __restrict__ x) {
    __shared__ float s[256];
    long long row = blockIdx.x;
    int tid = threadIdx.x;
    float v = fabsf(x[row*CML + tid]);
    s[tid] = v; __syncthreads();
    for (int o = 128; o > 0; o >>= 1) { if (tid < o) s[tid] += s[tid+o]; __syncthreads(); }
    if (tid == 0) atomicMax((int*)&g_gmax1, __float_as_int(s[0]));
}

__global__ void abs_colsum_max_kernel(const float* __restrict__ x) {
    const float* p = x + (long long)blockIdx.x*CML*CML;
    int j = threadIdx.x;
    float s = 0.f;
    for (int i = 0; i < CML; i++) s += fabsf(p[i*CML + j]);
    atomicMax((int*)&g_gmax2, __float_as_int(s));
}

__global__ void zinit_kernel(const float* __restrict__ x, float* __restrict__ z) {
    long long idx = (long long)blockIdx.x*256 + threadIdx.x;
    int j = (int)(idx & 255);
    int i = (int)((idx >> 8) & 255);
    long long bh = idx >> 16;
    float denom = g_gmax1 * g_gmax2;
    z[idx] = x[(bh << 16) + ((long long)j << 8) + i] / denom;
}

__global__ void conv_add_kernel(const float* __restrict__ v, const float* __restrict__ w,
                                float* __restrict__ oh) {
    long long idx = (long long)blockIdx.x*256 + threadIdx.x;
    int d = (int)(idx & 31);
    long long t = idx >> 5;
    int n = (int)(t & (CN-1));
    long long bh = t >> 12;
    int h = (int)(bh & 7);
    const float* wp = w + h*33;
    const float* vp = v + bh*(long long)CN*CDH + d;
    float s = 0.f;
    #pragma unroll
    for (int tt = 0; tt < 33; tt++) {
        int nn = n + tt - 16;
        if (nn >= 0 && nn < CN) s += vp[(long long)nn*CDH] * wp[tt];
    }
    oh[idx] += s;
}

__global__ void merge_heads_kernel(const float* __restrict__ oh, float* __restrict__ out) {
    long long idx = (long long)blockIdx.x*256 + threadIdx.x;
    int d = (int)(idx & 31);
    long long t = idx >> 5;
    int h = (int)(t & 7);
    t >>= 3;
    int n = (int)(t & (CN-1));
    int b = (int)(t >> 12);
    out[idx] = oh[((((long long)b*CH + h)*CN) + n)*CDH + d];
}

// ---------------- host orchestration -----------------------------------------
extern "C" void kernel_launch(void* const* d_in, const int* in_sizes, int n_in,
                              void* d_out, int out_size) {
    const float* x     = (const float*)d_in[0];
    const float* ln1_g = (const float*)d_in[1];
    const float* ln1_b = (const float*)d_in[2];
    const float* w_qkv = (const float*)d_in[3];
    const float* w_out = (const float*)d_in[4];
    const float* b_out = (const float*)d_in[5];
    const float* res_w = (const float*)d_in[6];
    const float* ln2_g = (const float*)d_in[7];
    const float* ln2_b = (const float*)d_in[8];
    const float* w1    = (const float*)d_in[9];
    const float* b1    = (const float*)d_in[10];
    const float* w2    = (const float*)d_in[11];
    const float* b2    = (const float*)d_in[12];

    float *Y,*XN,*Q,*K,*V,*QL,*KL,*X2,*A2,*Zb,*Z2,*XZ,*T1,*T2,*X1,*OH,*ONBD,*HID;
    cudaGetSymbolAddress((void**)&Y,   g_Y);
    cudaGetSymbolAddress((void**)&XN,  g_XN);
    cudaGetSymbolAddress((void**)&Q,   g_Q);
    cudaGetSymbolAddress((void**)&K,   g_K);
    cudaGetSymbolAddress((void**)&V,   g_V);
    cudaGetSymbolAddress((void**)&QL,  g_QL);
    cudaGetSymbolAddress((void**)&KL,  g_KL);
    cudaGetSymbolAddress((void**)&X2,  g_X2);
    cudaGetSymbolAddress((void**)&A2,  g_A2);
    cudaGetSymbolAddress((void**)&Zb,  g_Zb);
    cudaGetSymbolAddress((void**)&Z2,  g_Z2);
    cudaGetSymbolAddress((void**)&XZ,  g_XZ);
    cudaGetSymbolAddress((void**)&T1,  g_T1);
    cudaGetSymbolAddress((void**)&T2,  g_T2);
    cudaGetSymbolAddress((void**)&X1,  g_X1);
    cudaGetSymbolAddress((void**)&OH,  g_OH);
    cudaGetSymbolAddress((void**)&ONBD,g_ONBD);
    cudaGetSymbolAddress((void**)&HID, g_HID);

    cudaFuncSetAttribute(fused_attn1_kernel,
        cudaFuncAttributeMaxDynamicSharedMemorySize, FUSED_SMEM);
    cudaFuncSetAttribute(fused_attn3_kernel,
        cudaFuncAttributeMaxDynamicSharedMemorySize, FUSED_SMEM);

    cudaMemcpyAsync(Y, x, sizeof(float)*(size_t)CB*CN*CD, cudaMemcpyDeviceToDevice);

    const long long MM  = (long long)CML*CML;
    const long long SXD = (long long)CML*CDH;

    for (int blk = 0; blk < 2; blk++) {
        const float* p_ln1g = ln1_g + blk*CD;
        const float* p_ln1b = ln1_b + blk*CD;
        const float* p_wqkv = w_qkv + (long long)blk*CD*3*CINNER;
        const float* p_wout = w_out + (long long)blk*CINNER*CD;
        const float* p_bout = b_out + blk*CD;
        const float* p_resw = res_w + blk*CH*33;
        const float* p_ln2g = ln2_g + blk*CD;
        const float* p_ln2b = ln2_b + blk*CD;
        const float* p_w1   = w1 + (long long)blk*CD*2*CD;
        const float* p_b1   = b1 + blk*2*CD;
        const float* p_w2   = w2 + (long long)blk*2*CD*CD;
        const float* p_b2   = b2 + blk*CD;

        layernorm_kernel<<<CB*CN, 256>>>(Y, p_ln1g, p_ln1b, XN);

        // QKV + fused head-split (Q scaled by dh^-0.5)
        tc_gemm_kernel<6,false><<<dim3(6, 128), 256>>>(XN, p_wqkv, Q, K, V,
            CB*CN, 3*CINNER, CD, 0, 0, 0, 0.f, nullptr, nullptr);

        landmark_kernel<<<(CBH*CML*CDH)/256, 256>>>(Q, K, QL, KL);

        // attn2 = softmax(QL @ KL^T)
        tc_gemm_kernel<0,true><<<dim3(2, 2, CBH), 256>>>(QL, KL, A2, nullptr, nullptr,
            CML, CML, CDH, SXD, SXD, MM, 0.f, nullptr, nullptr);
        softmax256_kernel<<<(CBH*CML)/8, 256>>>(A2);

        // pinv (6 tf32 TC iterations)
        zero_gmax_kernel<<<1, 1>>>();
        abs_rowsum_max_kernel<<<CBH*CML, 256>>>(A2);
        abs_colsum_max_kernel<<<CBH, 256>>>(A2);
        zinit_kernel<<<(int)((CBH*MM)/256), 256>>>(A2, Zb);

        float* zc = Zb; float* zn = Z2;
        for (int it = 0; it < 6; it++) {
            tc_gemm_kernel<3,false><<<dim3(2,2,CBH), 256>>>(A2, zc, XZ, T1, nullptr,
                CML, CML, CML, MM, MM, MM, 7.0f, nullptr, nullptr);
            tc_gemm_kernel<1,false><<<dim3(2,2,CBH), 256>>>(XZ, T1, T2, nullptr, nullptr,
                CML, CML, CML, MM, MM, MM, 15.0f, nullptr, nullptr);
            tc_gemm_kernel<1,false><<<dim3(2,2,CBH), 256>>>(XZ, T2, T1, nullptr, nullptr,
                CML, CML, CML, MM, MM, MM, 13.0f, nullptr, nullptr);
            tc_gemm_kernel<2,false><<<dim3(2,2,CBH), 256>>>(zc, T1, zn, nullptr, nullptr,
                CML, CML, CML, MM, MM, MM, 0.25f, nullptr, nullptr);
            float* t = zc; zc = zn; zn = t;
        }

        // X1 = softmax(QL @ K^T) @ V  (fused online)
        fused_attn3_kernel<<<dim3(2, CBH), 256, FUSED_SMEM>>>(QL, K, V, X1);

        // X2 = pinv @ X1
        tc_n32_kernel<<<dim3(2, 1, CBH), 256>>>(zc, X1, X2, CML, CML, MM, SXD, SXD);

        // OH = softmax(Q @ KL^T) @ X2  (fused)
        fused_attn1_kernel<<<dim3(32, CBH), 256, FUSED_SMEM>>>(Q, KL, X2, OH);

        conv_add_kernel<<<(CB*CH*CN*CDH)/256, 256>>>(V, p_resw, OH);
        merge_heads_kernel<<<(CB*CN*CD)/256, 256>>>(OH, ONBD);

        tc_gemm_kernel<4,false><<<dim3(2, 128), 256>>>(ONBD, p_wout, Y, nullptr, nullptr,
            CB*CN, CD, CINNER, 0, 0, 0, 0.f, p_bout, Y);

        layernorm_kernel<<<CB*CN, 256>>>(Y, p_ln2g, p_ln2b, XN);
        tc_gemm_kernel<5,false><<<dim3(4, 128), 256>>>(XN, p_w1, HID, nullptr, nullptr,
            CB*CN, 2*CD, CD, 0, 0, 0, 0.f, p_b1, nullptr);
        tc_gemm_kernel<4,false><<<dim3(2, 128), 256>>>(HID, p_w2, Y, nullptr, nullptr,
            CB*CN, CD, 2*CD, 0, 0, 0, 0.f, p_b2, Y);
    }

    cudaMemcpyAsync(d_out, Y, sizeof(float)*(size_t)CB*CN*CD, cudaMemcpyDeviceToDevice);
}